// round 2
// baseline (speedup 1.0000x reference)
#include <cuda_runtime.h>
#include <cstdint>

// ---------------------------------------------------------------------------
// Problem constants
// ---------------------------------------------------------------------------
#define BB 2
#define H0 512
#define W0 512

// scratch layout (floats)
#define SZ_T1    16777216ull   // 2*32*512*512
#define SZ_FEA1  16777216ull
#define SZ_T2     8388608ull   // 2*64*256*256
#define SZ_FEA2   8388608ull
#define SZ_T3     3145728ull   // 2*96*128*128
#define SZ_FEA3   3145728ull
#define SZ_Z       524288ull   // 2*512*512
#define SZ_ZR1     131072ull
#define SZ_ZR2      32768ull
#define SZ_ACC    1572864ull   // 2*3*512*512
#define SZ_FLOW   1048576ull   // 2*2*512*512

#define O_T1      0ull
#define O_FEA1_0  (O_T1 + SZ_T1)
#define O_FEA1_1  (O_FEA1_0 + SZ_FEA1)
#define O_T2      (O_FEA1_1 + SZ_FEA1)
#define O_FEA2_0  (O_T2 + SZ_T2)
#define O_FEA2_1  (O_FEA2_0 + SZ_FEA2)
#define O_T3      (O_FEA2_1 + SZ_FEA2)
#define O_FEA3_0  (O_T3 + SZ_T3)
#define O_FEA3_1  (O_FEA3_0 + SZ_FEA3)
#define O_Z       (O_FEA3_1 + SZ_FEA3)
#define O_ZR1     (O_Z + SZ_Z)
#define O_ZR2     (O_ZR1 + SZ_ZR1)
#define O_ACC     (O_ZR2 + SZ_ZR2)
#define O_FLOW    (O_ACC + SZ_ACC)
#define SCRATCH_TOTAL (O_FLOW + SZ_FLOW)   // 88,244,224 floats ~ 353 MB

__device__ float g_scratch[SCRATCH_TOTAL];

// ---------------------------------------------------------------------------
// Direct 3x3 conv + PReLU. 16x16 output tile, 32 out-channels per block in
// registers, per-ic input tile + 288 weights staged through SMEM.
// ---------------------------------------------------------------------------
template <int IC, int STRIDE>
__global__ __launch_bounds__(256)
void conv3x3_k(const float* __restrict__ in, const float* __restrict__ wgt,
               const float* __restrict__ bias, const float* __restrict__ prelu_a,
               int aidx, float* __restrict__ out,
               int Hin, int Win, int OC, int ocBlocks)
{
    constexpr int TS = 16 * STRIDE + 3 - STRIDE;   // 18 (s1) / 33 (s2)
    __shared__ float s_in[TS * TS];
    __shared__ float s_w[32 * 9];

    const int tx = threadIdx.x, ty = threadIdx.y;
    const int tid = ty * 16 + tx;
    const int bz  = blockIdx.z;
    const int ocb = bz % ocBlocks;
    const int b   = bz / ocBlocks;
    const int oc0 = ocb * 32;
    const int Hout = Hin / STRIDE;
    const int Wout = Win / STRIDE;
    const int ox = blockIdx.x * 16 + tx;
    const int oy = blockIdx.y * 16 + ty;
    const int ix0 = blockIdx.x * 16 * STRIDE - 1;
    const int iy0 = blockIdx.y * 16 * STRIDE - 1;

    float acc[32];
#pragma unroll
    for (int o = 0; o < 32; o++) acc[o] = 0.f;

    for (int ic = 0; ic < IC; ic++) {
        __syncthreads();
        const float* ip = in + ((size_t)(b * IC + ic)) * Hin * Win;
        for (int i = tid; i < TS * TS; i += 256) {
            int gy = iy0 + i / TS;
            int gx = ix0 + i % TS;
            float v = 0.f;
            if (gy >= 0 && gy < Hin && gx >= 0 && gx < Win) v = ip[gy * Win + gx];
            s_in[i] = v;
        }
        // FIX (R1): 288 weights staged by a 256-thread block -> strided loop.
        for (int i = tid; i < 288; i += 256) {
            int o = i / 9, k = i % 9;
            s_w[i] = wgt[((size_t)(oc0 + o) * IC + ic) * 9 + k];
        }
        __syncthreads();

        float v[9];
        const int ly = ty * STRIDE, lx = tx * STRIDE;
#pragma unroll
        for (int ky = 0; ky < 3; ky++)
#pragma unroll
            for (int kx = 0; kx < 3; kx++)
                v[ky * 3 + kx] = s_in[(ly + ky) * TS + lx + kx];

#pragma unroll
        for (int o = 0; o < 32; o++) {
            float a = acc[o];
            const float* w9 = &s_w[o * 9];
#pragma unroll
            for (int k = 0; k < 9; k++) a = fmaf(v[k], w9[k], a);
            acc[o] = a;
        }
    }

    const float slope = prelu_a[aidx];
#pragma unroll
    for (int o = 0; o < 32; o++) {
        float val = acc[o] + bias[oc0 + o];
        if (val < 0.f) val *= slope;
        out[(((size_t)b * OC + oc0 + o) * Hout + oy) * Wout + ox] = val;
    }
}

// ---------------------------------------------------------------------------
// z = param_scale * mean_c |p0 - backwarp(p1, flow)|  (p = 2*img - 1)
// ---------------------------------------------------------------------------
__global__ void z_kernel(const float* __restrict__ i0, const float* __restrict__ i1,
                         const float* __restrict__ flow, const float* __restrict__ pscale,
                         float* __restrict__ z, int h, int w, int n)
{
    int p = blockIdx.x * 256 + threadIdx.x;
    if (p >= n) return;
    const int hw = h * w;
    const int b = p / hw, pp = p % hw;
    const int y = pp / w, x = pp - y * w;

    float f0 = flow[((size_t)b * 2 + 0) * hw + pp];
    float f1 = flow[((size_t)b * 2 + 1) * hw + pp];
    float px = fminf(fmaxf((float)x + f0, 0.f), (float)(w - 1));
    float py = fminf(fmaxf((float)y + f1, 0.f), (float)(h - 1));
    float x0f = floorf(px), y0f = floorf(py);
    int x0 = (int)x0f, y0 = (int)y0f;
    int x1 = min(x0 + 1, w - 1), y1 = min(y0 + 1, h - 1);
    float wx = px - x0f, wy = py - y0f;
    float w00 = (1.f - wx) * (1.f - wy), w10 = wx * (1.f - wy);
    float w01 = (1.f - wx) * wy,        w11 = wx * wy;

    float err = 0.f;
#pragma unroll
    for (int c = 0; c < 3; c++) {
        const float* sp = i1 + ((size_t)(b * 3 + c)) * hw;
        float g = sp[y0 * w + x0] * w00 + sp[y0 * w + x1] * w10 +
                  sp[y1 * w + x0] * w01 + sp[y1 * w + x1] * w11;
        float pg = 2.f * g - 1.f;
        float p0 = 2.f * i0[((size_t)(b * 3 + c)) * hw + pp] - 1.f;
        err += fabsf(p0 - pg);
    }
    err *= (1.f / 3.f);
    z[p] = pscale[0] * err;
}

// ---------------------------------------------------------------------------
// bilinear resize, single channel, exact (i+0.5)*scale - 0.5 coords
// ---------------------------------------------------------------------------
__global__ void resize_k(const float* __restrict__ in, float* __restrict__ out,
                         int hi, int wi, int ho, int wo, int n)
{
    int p = blockIdx.x * 256 + threadIdx.x;
    if (p >= n) return;
    const int hwO = ho * wo;
    const int b = p / hwO, pp = p % hwO;
    const int y = pp / wo, x = pp - y * wo;

    float sy = (float)hi / (float)ho;
    float sx = (float)wi / (float)wo;
    float py = fminf(fmaxf(((float)y + 0.5f) * sy - 0.5f, 0.f), (float)(hi - 1));
    float px = fminf(fmaxf(((float)x + 0.5f) * sx - 0.5f, 0.f), (float)(wi - 1));
    float y0f = floorf(py), x0f = floorf(px);
    int y0 = (int)y0f, x0 = (int)x0f;
    int y1 = min(y0 + 1, hi - 1), x1 = min(x0 + 1, wi - 1);
    float wy = py - y0f, wx = px - x0f;

    const float* sp = in + (size_t)b * hi * wi;
    float r0 = sp[y0 * wi + x0] * (1.f - wx) + sp[y0 * wi + x1] * wx;
    float r1 = sp[y1 * wi + x0] * (1.f - wx) + sp[y1 * wi + x1] * wx;
    out[p] = r0 * (1.f - wy) + r1 * wy;
}

// ---------------------------------------------------------------------------
// softsplat scatter: acc[b, {(-f*ez).x, (-f*ez).y, ez}, h, w] += bilinear
// ---------------------------------------------------------------------------
__global__ void splat_k(const float* __restrict__ flow, const float* __restrict__ zz,
                        const float* __restrict__ tvec, int oneMinus,
                        float* __restrict__ acc, int h, int w, int n)
{
    int p = blockIdx.x * 256 + threadIdx.x;
    if (p >= n) return;
    const int hw = h * w;
    const int b = p / hw, pp = p % hw;
    const int y = pp / w, x = pp - y * w;

    float tt = tvec[b];
    if (oneMinus) tt = 1.f - tt;
    float f0 = tt * flow[((size_t)b * 2 + 0) * hw + pp];
    float f1 = tt * flow[((size_t)b * 2 + 1) * hw + pp];
    float ez = expf(zz[(size_t)b * hw + pp]);
    float v0 = -f0 * ez, v1 = -f1 * ez;

    float fx = (float)x + f0, fy = (float)y + f1;
    float x0f = floorf(fx), y0f = floorf(fy);
    int x0 = (int)x0f, y0 = (int)y0f;
    int x1 = x0 + 1, y1 = y0 + 1;
    float wx1 = fx - x0f, wy1 = fy - y0f;
    float wx0 = 1.f - wx1, wy0 = 1.f - wy1;

    float* a0 = acc + (size_t)b * 3 * hw;
    int cx[4] = {x0, x1, x0, x1};
    int cy[4] = {y0, y0, y1, y1};
    float cw[4] = {wx0 * wy0, wx1 * wy0, wx0 * wy1, wx1 * wy1};
#pragma unroll
    for (int k = 0; k < 4; k++) {
        if (cx[k] >= 0 && cx[k] < w && cy[k] >= 0 && cy[k] < h) {
            int q = cy[k] * w + cx[k];
            float wt = cw[k];
            atomicAdd(a0 + q, v0 * wt);
            atomicAdd(a0 + hw + q, v1 * wt);
            atomicAdd(a0 + 2 * hw + q, ez * wt);
        }
    }
}

__global__ void norm_k(const float* __restrict__ acc, float* __restrict__ flw,
                       int hw, int n)
{
    int p = blockIdx.x * 256 + threadIdx.x;
    if (p >= n) return;
    const int b = p / hw, pp = p % hw;
    float d = acc[((size_t)b * 3 + 2) * hw + pp] + 1e-7f;
    flw[((size_t)b * 2 + 0) * hw + pp] = acc[((size_t)b * 3 + 0) * hw + pp] / d;
    flw[((size_t)b * 2 + 1) * hw + pp] = acc[((size_t)b * 3 + 1) * hw + pp] / d;
}

// ---------------------------------------------------------------------------
// backwarp src (C channels) with flow, write into packed output tensor
// at channel offset c0 within CT total channels. grid.y = channel chunk (32).
// ---------------------------------------------------------------------------
__global__ void backwarp_out_k(const float* __restrict__ src, int C,
                               const float* __restrict__ flow, float* __restrict__ out,
                               int CT, int c0, int h, int w, int n)
{
    int p = blockIdx.x * 256 + threadIdx.x;
    if (p >= n) return;
    const int hw = h * w;
    const int b = p / hw, pp = p % hw;
    const int y = pp / w, x = pp - y * w;

    float f0 = flow[((size_t)b * 2 + 0) * hw + pp];
    float f1 = flow[((size_t)b * 2 + 1) * hw + pp];
    float px = fminf(fmaxf((float)x + f0, 0.f), (float)(w - 1));
    float py = fminf(fmaxf((float)y + f1, 0.f), (float)(h - 1));
    float x0f = floorf(px), y0f = floorf(py);
    int x0 = (int)x0f, y0 = (int)y0f;
    int x1 = min(x0 + 1, w - 1), y1 = min(y0 + 1, h - 1);
    float wx = px - x0f, wy = py - y0f;
    float w00 = (1.f - wx) * (1.f - wy), w10 = wx * (1.f - wy);
    float w01 = (1.f - wx) * wy,        w11 = wx * wy;

    int cbeg = blockIdx.y * 32;
    int cend = min(cbeg + 32, C);
    for (int c = cbeg; c < cend; c++) {
        const float* sp = src + ((size_t)b * C + c) * hw;
        float g = sp[y0 * w + x0] * w00 + sp[y0 * w + x1] * w10 +
                  sp[y1 * w + x0] * w01 + sp[y1 * w + x1] * w11;
        out[(((size_t)b * CT + c0 + c) * h + y) * w + x] = g;
    }
}

// ---------------------------------------------------------------------------
// Orchestration
// ---------------------------------------------------------------------------
static inline int cdiv(int a, int b) { return (a + b - 1) / b; }

extern "C" void kernel_launch(void* const* d_in, const int* in_sizes, int n_in,
                              void* d_out, int out_size)
{
    const float* in0   = (const float*)d_in[0];
    const float* in1   = (const float*)d_in[1];
    const float* tvec  = (const float*)d_in[2];
    const float* f01[3] = {(const float*)d_in[3], (const float*)d_in[4], (const float*)d_in[5]};
    const float* f10[3] = {(const float*)d_in[6], (const float*)d_in[7], (const float*)d_in[8]};
    const float* W[6]  = {(const float*)d_in[9],  (const float*)d_in[11], (const float*)d_in[13],
                          (const float*)d_in[15], (const float*)d_in[17], (const float*)d_in[19]};
    const float* Bs[6] = {(const float*)d_in[10], (const float*)d_in[12], (const float*)d_in[14],
                          (const float*)d_in[16], (const float*)d_in[18], (const float*)d_in[20]};
    const float* prelu  = (const float*)d_in[21];
    const float* pscale = (const float*)d_in[22];
    float* out = (float*)d_out;

    float* S = nullptr;
    cudaGetSymbolAddress((void**)&S, g_scratch);

    dim3 blk(16, 16);

    // ---- feature extraction for both images ----
    for (int img = 0; img < 2; img++) {
        const float* x = img ? in1 : in0;
        float* fea1 = S + (img ? O_FEA1_1 : O_FEA1_0);
        float* fea2 = S + (img ? O_FEA2_1 : O_FEA2_0);
        float* fea3 = S + (img ? O_FEA3_1 : O_FEA3_0);

        conv3x3_k<3, 1><<<dim3(32, 32, BB * 1), blk>>>(x,        W[0], Bs[0], prelu, 0, S + O_T1, 512, 512, 32, 1);
        conv3x3_k<32, 1><<<dim3(32, 32, BB * 1), blk>>>(S + O_T1, W[1], Bs[1], prelu, 1, fea1,     512, 512, 32, 1);
        conv3x3_k<32, 2><<<dim3(16, 16, BB * 2), blk>>>(fea1,     W[2], Bs[2], prelu, 2, S + O_T2, 512, 512, 64, 2);
        conv3x3_k<64, 1><<<dim3(16, 16, BB * 2), blk>>>(S + O_T2, W[3], Bs[3], prelu, 3, fea2,     256, 256, 64, 2);
        conv3x3_k<64, 2><<<dim3(8, 8, BB * 3), blk>>>(fea2,       W[4], Bs[4], prelu, 4, S + O_T3, 256, 256, 96, 3);
        conv3x3_k<96, 1><<<dim3(8, 8, BB * 3), blk>>>(S + O_T3,   W[5], Bs[5], prelu, 5, fea3,     128, 128, 96, 3);
    }

    float* L0 = out;                 // (B,70,512,512)
    float* L1 = out + 36700160ull;   // (B,128,256,256)
    float* L2 = out + 53477376ull;   // (B,192,128,128)

    // ---- splat maps, both directions ----
    for (int dir = 0; dir < 2; dir++) {
        const float* i0 = dir ? in1 : in0;
        const float* i1sec = dir ? in0 : in1;
        const float* const* fl = dir ? f10 : f01;
        const float* fea1 = S + (dir ? O_FEA1_1 : O_FEA1_0);
        const float* fea2 = S + (dir ? O_FEA2_1 : O_FEA2_0);
        const float* fea3 = S + (dir ? O_FEA3_1 : O_FEA3_0);

        const int n0 = BB * 512 * 512;
        z_kernel<<<cdiv(n0, 256), 256>>>(i0, i1sec, fl[0], pscale, S + O_Z, 512, 512, n0);
        const int nr1 = BB * 256 * 256, nr2 = BB * 128 * 128;
        resize_k<<<cdiv(nr1, 256), 256>>>(S + O_Z, S + O_ZR1, 512, 512, 256, 256, nr1);
        resize_k<<<cdiv(nr2, 256), 256>>>(S + O_Z, S + O_ZR2, 512, 512, 128, 128, nr2);

        for (int s = 0; s < 3; s++) {
            const int hh = 512 >> s, ww = 512 >> s;
            const int hw = hh * ww, n = BB * hw;
            const float* zl = (s == 0) ? (S + O_Z) : ((s == 1) ? (S + O_ZR1) : (S + O_ZR2));

            cudaMemsetAsync(S + O_ACC, 0, sizeof(float) * (size_t)BB * 3 * hw, 0);
            splat_k<<<cdiv(n, 256), 256>>>(fl[s], zl, tvec, dir, S + O_ACC, hh, ww, n);
            norm_k<<<cdiv(n, 256), 256>>>(S + O_ACC, S + O_FLOW, hw, n);

            if (s == 0) {
                backwarp_out_k<<<dim3(cdiv(n, 256), 1), 256>>>(i0,   3,  S + O_FLOW, L0, 70, dir ? 35 : 0, hh, ww, n);
                backwarp_out_k<<<dim3(cdiv(n, 256), 1), 256>>>(fea1, 32, S + O_FLOW, L0, 70, dir ? 38 : 3, hh, ww, n);
            } else if (s == 1) {
                backwarp_out_k<<<dim3(cdiv(n, 256), 2), 256>>>(fea2, 64, S + O_FLOW, L1, 128, dir ? 64 : 0, hh, ww, n);
            } else {
                backwarp_out_k<<<dim3(cdiv(n, 256), 3), 256>>>(fea3, 96, S + O_FLOW, L2, 192, dir ? 96 : 0, hh, ww, n);
            }
        }
    }
}

// round 3
// speedup vs baseline: 1.5003x; 1.5003x over previous
#include <cuda_runtime.h>
#include <cstdint>

// ---------------------------------------------------------------------------
// Problem constants
// ---------------------------------------------------------------------------
#define BB 2
#define H0 512
#define W0 512

// scratch layout (floats)
#define SZ_T1    16777216ull   // 2*32*512*512
#define SZ_FEA1  16777216ull
#define SZ_T2     8388608ull   // 2*64*256*256
#define SZ_FEA2   8388608ull
#define SZ_T3     3145728ull   // 2*96*128*128
#define SZ_FEA3   3145728ull
#define SZ_Z       524288ull   // 2*512*512
#define SZ_ZR1     131072ull
#define SZ_ZR2      32768ull
#define SZ_ACC    1572864ull   // 2*3*512*512
#define SZ_FLOW   1048576ull   // 2*2*512*512

#define O_T1      0ull
#define O_FEA1_0  (O_T1 + SZ_T1)
#define O_FEA1_1  (O_FEA1_0 + SZ_FEA1)
#define O_T2      (O_FEA1_1 + SZ_FEA1)
#define O_FEA2_0  (O_T2 + SZ_T2)
#define O_FEA2_1  (O_FEA2_0 + SZ_FEA2)
#define O_T3      (O_FEA2_1 + SZ_FEA2)
#define O_FEA3_0  (O_T3 + SZ_T3)
#define O_FEA3_1  (O_FEA3_0 + SZ_FEA3)
#define O_Z       (O_FEA3_1 + SZ_FEA3)
#define O_ZR1     (O_Z + SZ_Z)
#define O_ZR2     (O_ZR1 + SZ_ZR1)
#define O_ACC     (O_ZR2 + SZ_ZR2)
#define O_FLOW    (O_ACC + SZ_ACC)
#define SCRATCH_TOTAL (O_FLOW + SZ_FLOW)   // 88,244,224 floats ~ 353 MB

__device__ float g_scratch[SCRATCH_TOTAL];

// ---------------------------------------------------------------------------
// Register-tiled 3x3 conv + PReLU.
//  - Block: 256 threads = 64 pixel-slots x 4 oc-slots. 32 out-channels/block.
//  - Each thread: PX=2 x PY pixels, 8 ocs -> 8*PX*PY accumulators.
//  - Per ic: input patch -> registers (reused by all 9 taps), weights staged
//    k-major s_w[9][32] so each tap reads 8 ocs via two float4 LDS.
//  - stride1: PY=2 (16x16 tile), stride2: PY=1 (16x8 tile).
// ---------------------------------------------------------------------------
template <int IC, int STRIDE, int PY>
__global__ __launch_bounds__(256)
void conv3x3_k(const float* __restrict__ in, const float* __restrict__ wgt,
               const float* __restrict__ bias, const float* __restrict__ prelu_a,
               int aidx, float* __restrict__ out,
               int Hin, int Win, int OC, int ocBlocks)
{
    constexpr int PX = 2;
    constexpr int OUT_TW = 16;                 // tile width (pixels)
    constexpr int OUT_TH = 8 * PY;             // tile height
    constexpr int TS_W = OUT_TW * STRIDE + 2;  // input tile W
    constexpr int TS_H = OUT_TH * STRIDE + 2;  // input tile H
    constexpr int PW = (PX - 1) * STRIDE + 3;  // per-thread patch W
    constexpr int PH = (PY - 1) * STRIDE + 3;  // per-thread patch H

    __shared__ __align__(16) float s_in[TS_H * TS_W];
    __shared__ __align__(16) float s_w[9 * 32];

    const int tid = threadIdx.x;
    const int oo  = tid & 3;          // oc slot (8 ocs each)
    const int slot = tid >> 2;        // 64 pixel slots
    const int sx = slot & 7;
    const int sy = slot >> 3;

    const int bz  = blockIdx.z;
    const int ocb = bz % ocBlocks;
    const int b   = bz / ocBlocks;
    const int oc0 = ocb * 32;
    const int Hout = Hin / STRIDE;
    const int Wout = Win / STRIDE;

    const int ox = blockIdx.x * OUT_TW + sx * PX;
    const int oy = blockIdx.y * OUT_TH + sy * PY;
    const int ix0 = blockIdx.x * OUT_TW * STRIDE - 1;
    const int iy0 = blockIdx.y * OUT_TH * STRIDE - 1;

    float acc[8][PX * PY];
#pragma unroll
    for (int o = 0; o < 8; o++)
#pragma unroll
        for (int p = 0; p < PX * PY; p++) acc[o][p] = 0.f;

    const int ly = sy * PY * STRIDE;   // patch origin in s_in
    const int lx = sx * PX * STRIDE;

    for (int ic = 0; ic < IC; ic++) {
        __syncthreads();
        const float* ip = in + ((size_t)(b * IC + ic)) * Hin * Win;
#pragma unroll 2
        for (int i = tid; i < TS_H * TS_W; i += 256) {
            int gy = iy0 + i / TS_W;
            int gx = ix0 + i % TS_W;
            float v = 0.f;
            if (gy >= 0 && gy < Hin && gx >= 0 && gx < Win) v = ip[gy * Win + gx];
            s_in[i] = v;
        }
        // k-major weights: s_w[k*32 + oc]
        for (int i = tid; i < 288; i += 256) {
            int k = i >> 5, oc = i & 31;
            s_w[i] = wgt[((size_t)(oc0 + oc) * IC + ic) * 9 + k];
        }
        __syncthreads();

        float v[PH][PW];
#pragma unroll
        for (int r = 0; r < PH; r++)
#pragma unroll
            for (int c = 0; c < PW; c++)
                v[r][c] = s_in[(ly + r) * TS_W + lx + c];

#pragma unroll
        for (int k = 0; k < 9; k++) {
            const int ky = k / 3, kx = k % 3;
            const float4 wA = *reinterpret_cast<const float4*>(&s_w[k * 32 + oo * 8]);
            const float4 wB = *reinterpret_cast<const float4*>(&s_w[k * 32 + oo * 8 + 4]);
            const float w8[8] = {wA.x, wA.y, wA.z, wA.w, wB.x, wB.y, wB.z, wB.w};
#pragma unroll
            for (int o = 0; o < 8; o++)
#pragma unroll
                for (int py = 0; py < PY; py++)
#pragma unroll
                    for (int px = 0; px < PX; px++)
                        acc[o][py * PX + px] =
                            fmaf(v[py * STRIDE + ky][px * STRIDE + kx], w8[o],
                                 acc[o][py * PX + px]);
        }
    }

    const float slope = prelu_a[aidx];
#pragma unroll
    for (int o = 0; o < 8; o++) {
        const int oc = oc0 + oo * 8 + o;
        const float bv = bias[oc];
        float* op = out + (((size_t)b * OC + oc) * Hout) * Wout;
#pragma unroll
        for (int py = 0; py < PY; py++)
#pragma unroll
            for (int px = 0; px < PX; px++) {
                float val = acc[o][py * PX + px] + bv;
                if (val < 0.f) val *= slope;
                op[(size_t)(oy + py) * Wout + ox + px] = val;
            }
    }
}

// ---------------------------------------------------------------------------
// z = param_scale * mean_c |p0 - backwarp(p1, flow)|  (p = 2*img - 1)
// ---------------------------------------------------------------------------
__global__ void z_kernel(const float* __restrict__ i0, const float* __restrict__ i1,
                         const float* __restrict__ flow, const float* __restrict__ pscale,
                         float* __restrict__ z, int h, int w, int n)
{
    int p = blockIdx.x * 256 + threadIdx.x;
    if (p >= n) return;
    const int hw = h * w;
    const int b = p / hw, pp = p % hw;
    const int y = pp / w, x = pp - y * w;

    float f0 = flow[((size_t)b * 2 + 0) * hw + pp];
    float f1 = flow[((size_t)b * 2 + 1) * hw + pp];
    float px = fminf(fmaxf((float)x + f0, 0.f), (float)(w - 1));
    float py = fminf(fmaxf((float)y + f1, 0.f), (float)(h - 1));
    float x0f = floorf(px), y0f = floorf(py);
    int x0 = (int)x0f, y0 = (int)y0f;
    int x1 = min(x0 + 1, w - 1), y1 = min(y0 + 1, h - 1);
    float wx = px - x0f, wy = py - y0f;
    float w00 = (1.f - wx) * (1.f - wy), w10 = wx * (1.f - wy);
    float w01 = (1.f - wx) * wy,        w11 = wx * wy;

    float err = 0.f;
#pragma unroll
    for (int c = 0; c < 3; c++) {
        const float* sp = i1 + ((size_t)(b * 3 + c)) * hw;
        float g = sp[y0 * w + x0] * w00 + sp[y0 * w + x1] * w10 +
                  sp[y1 * w + x0] * w01 + sp[y1 * w + x1] * w11;
        float pg = 2.f * g - 1.f;
        float p0 = 2.f * i0[((size_t)(b * 3 + c)) * hw + pp] - 1.f;
        err += fabsf(p0 - pg);
    }
    err *= (1.f / 3.f);
    z[p] = pscale[0] * err;
}

// ---------------------------------------------------------------------------
// bilinear resize, single channel, exact (i+0.5)*scale - 0.5 coords
// ---------------------------------------------------------------------------
__global__ void resize_k(const float* __restrict__ in, float* __restrict__ out,
                         int hi, int wi, int ho, int wo, int n)
{
    int p = blockIdx.x * 256 + threadIdx.x;
    if (p >= n) return;
    const int hwO = ho * wo;
    const int b = p / hwO, pp = p % hwO;
    const int y = pp / wo, x = pp - y * wo;

    float sy = (float)hi / (float)ho;
    float sx = (float)wi / (float)wo;
    float py = fminf(fmaxf(((float)y + 0.5f) * sy - 0.5f, 0.f), (float)(hi - 1));
    float px = fminf(fmaxf(((float)x + 0.5f) * sx - 0.5f, 0.f), (float)(wi - 1));
    float y0f = floorf(py), x0f = floorf(px);
    int y0 = (int)y0f, x0 = (int)x0f;
    int y1 = min(y0 + 1, hi - 1), x1 = min(x0 + 1, wi - 1);
    float wy = py - y0f, wx = px - x0f;

    const float* sp = in + (size_t)b * hi * wi;
    float r0 = sp[y0 * wi + x0] * (1.f - wx) + sp[y0 * wi + x1] * wx;
    float r1 = sp[y1 * wi + x0] * (1.f - wx) + sp[y1 * wi + x1] * wx;
    out[p] = r0 * (1.f - wy) + r1 * wy;
}

// ---------------------------------------------------------------------------
// softsplat scatter: acc[b, {(-f*ez).x, (-f*ez).y, ez}, h, w] += bilinear
// ---------------------------------------------------------------------------
__global__ void splat_k(const float* __restrict__ flow, const float* __restrict__ zz,
                        const float* __restrict__ tvec, int oneMinus,
                        float* __restrict__ acc, int h, int w, int n)
{
    int p = blockIdx.x * 256 + threadIdx.x;
    if (p >= n) return;
    const int hw = h * w;
    const int b = p / hw, pp = p % hw;
    const int y = pp / w, x = pp - y * w;

    float tt = tvec[b];
    if (oneMinus) tt = 1.f - tt;
    float f0 = tt * flow[((size_t)b * 2 + 0) * hw + pp];
    float f1 = tt * flow[((size_t)b * 2 + 1) * hw + pp];
    float ez = expf(zz[(size_t)b * hw + pp]);
    float v0 = -f0 * ez, v1 = -f1 * ez;

    float fx = (float)x + f0, fy = (float)y + f1;
    float x0f = floorf(fx), y0f = floorf(fy);
    int x0 = (int)x0f, y0 = (int)y0f;
    int x1 = x0 + 1, y1 = y0 + 1;
    float wx1 = fx - x0f, wy1 = fy - y0f;
    float wx0 = 1.f - wx1, wy0 = 1.f - wy1;

    float* a0 = acc + (size_t)b * 3 * hw;
    int cx[4] = {x0, x1, x0, x1};
    int cy[4] = {y0, y0, y1, y1};
    float cw[4] = {wx0 * wy0, wx1 * wy0, wx0 * wy1, wx1 * wy1};
#pragma unroll
    for (int k = 0; k < 4; k++) {
        if (cx[k] >= 0 && cx[k] < w && cy[k] >= 0 && cy[k] < h) {
            int q = cy[k] * w + cx[k];
            float wt = cw[k];
            atomicAdd(a0 + q, v0 * wt);
            atomicAdd(a0 + hw + q, v1 * wt);
            atomicAdd(a0 + 2 * hw + q, ez * wt);
        }
    }
}

__global__ void norm_k(const float* __restrict__ acc, float* __restrict__ flw,
                       int hw, int n)
{
    int p = blockIdx.x * 256 + threadIdx.x;
    if (p >= n) return;
    const int b = p / hw, pp = p % hw;
    float d = acc[((size_t)b * 3 + 2) * hw + pp] + 1e-7f;
    flw[((size_t)b * 2 + 0) * hw + pp] = acc[((size_t)b * 3 + 0) * hw + pp] / d;
    flw[((size_t)b * 2 + 1) * hw + pp] = acc[((size_t)b * 3 + 1) * hw + pp] / d;
}

// ---------------------------------------------------------------------------
// backwarp src (C channels) with flow, write into packed output tensor
// at channel offset c0 within CT total channels. grid.y = channel chunk (32).
// ---------------------------------------------------------------------------
__global__ void backwarp_out_k(const float* __restrict__ src, int C,
                               const float* __restrict__ flow, float* __restrict__ out,
                               int CT, int c0, int h, int w, int n)
{
    int p = blockIdx.x * 256 + threadIdx.x;
    if (p >= n) return;
    const int hw = h * w;
    const int b = p / hw, pp = p % hw;
    const int y = pp / w, x = pp - y * w;

    float f0 = flow[((size_t)b * 2 + 0) * hw + pp];
    float f1 = flow[((size_t)b * 2 + 1) * hw + pp];
    float px = fminf(fmaxf((float)x + f0, 0.f), (float)(w - 1));
    float py = fminf(fmaxf((float)y + f1, 0.f), (float)(h - 1));
    float x0f = floorf(px), y0f = floorf(py);
    int x0 = (int)x0f, y0 = (int)y0f;
    int x1 = min(x0 + 1, w - 1), y1 = min(y0 + 1, h - 1);
    float wx = px - x0f, wy = py - y0f;
    float w00 = (1.f - wx) * (1.f - wy), w10 = wx * (1.f - wy);
    float w01 = (1.f - wx) * wy,        w11 = wx * wy;

    int cbeg = blockIdx.y * 32;
    int cend = min(cbeg + 32, C);
    for (int c = cbeg; c < cend; c++) {
        const float* sp = src + ((size_t)b * C + c) * hw;
        float g = sp[y0 * w + x0] * w00 + sp[y0 * w + x1] * w10 +
                  sp[y1 * w + x0] * w01 + sp[y1 * w + x1] * w11;
        out[(((size_t)b * CT + c0 + c) * h + y) * w + x] = g;
    }
}

// ---------------------------------------------------------------------------
// Orchestration
// ---------------------------------------------------------------------------
static inline int cdiv(int a, int b) { return (a + b - 1) / b; }

extern "C" void kernel_launch(void* const* d_in, const int* in_sizes, int n_in,
                              void* d_out, int out_size)
{
    const float* in0   = (const float*)d_in[0];
    const float* in1   = (const float*)d_in[1];
    const float* tvec  = (const float*)d_in[2];
    const float* f01[3] = {(const float*)d_in[3], (const float*)d_in[4], (const float*)d_in[5]};
    const float* f10[3] = {(const float*)d_in[6], (const float*)d_in[7], (const float*)d_in[8]};
    const float* W[6]  = {(const float*)d_in[9],  (const float*)d_in[11], (const float*)d_in[13],
                          (const float*)d_in[15], (const float*)d_in[17], (const float*)d_in[19]};
    const float* Bs[6] = {(const float*)d_in[10], (const float*)d_in[12], (const float*)d_in[14],
                          (const float*)d_in[16], (const float*)d_in[18], (const float*)d_in[20]};
    const float* prelu  = (const float*)d_in[21];
    const float* pscale = (const float*)d_in[22];
    float* out = (float*)d_out;

    float* S = nullptr;
    cudaGetSymbolAddress((void**)&S, g_scratch);

    // ---- feature extraction for both images ----
    // stride1 layers: 16x16 output tile (PY=2); stride2: 16x8 tile (PY=1)
    for (int img = 0; img < 2; img++) {
        const float* x = img ? in1 : in0;
        float* fea1 = S + (img ? O_FEA1_1 : O_FEA1_0);
        float* fea2 = S + (img ? O_FEA2_1 : O_FEA2_0);
        float* fea3 = S + (img ? O_FEA3_1 : O_FEA3_0);

        conv3x3_k<3, 1, 2><<<dim3(32, 32, 2), 256>>>(x,        W[0], Bs[0], prelu, 0, S + O_T1, 512, 512, 32, 1);
        conv3x3_k<32, 1, 2><<<dim3(32, 32, 2), 256>>>(S + O_T1, W[1], Bs[1], prelu, 1, fea1,     512, 512, 32, 1);
        conv3x3_k<32, 2, 1><<<dim3(16, 32, 4), 256>>>(fea1,     W[2], Bs[2], prelu, 2, S + O_T2, 512, 512, 64, 2);
        conv3x3_k<64, 1, 2><<<dim3(16, 16, 4), 256>>>(S + O_T2, W[3], Bs[3], prelu, 3, fea2,     256, 256, 64, 2);
        conv3x3_k<64, 2, 1><<<dim3(8, 16, 6), 256>>>(fea2,      W[4], Bs[4], prelu, 4, S + O_T3, 256, 256, 96, 3);
        conv3x3_k<96, 1, 2><<<dim3(8, 8, 6), 256>>>(S + O_T3,   W[5], Bs[5], prelu, 5, fea3,     128, 128, 96, 3);
    }

    float* L0 = out;                 // (B,70,512,512)
    float* L1 = out + 36700160ull;   // (B,128,256,256)
    float* L2 = out + 53477376ull;   // (B,192,128,128)

    // ---- splat maps, both directions ----
    for (int dir = 0; dir < 2; dir++) {
        const float* i0 = dir ? in1 : in0;
        const float* i1sec = dir ? in0 : in1;
        const float* const* fl = dir ? f10 : f01;
        const float* fea1 = S + (dir ? O_FEA1_1 : O_FEA1_0);
        const float* fea2 = S + (dir ? O_FEA2_1 : O_FEA2_0);
        const float* fea3 = S + (dir ? O_FEA3_1 : O_FEA3_0);

        const int n0 = BB * 512 * 512;
        z_kernel<<<cdiv(n0, 256), 256>>>(i0, i1sec, fl[0], pscale, S + O_Z, 512, 512, n0);
        const int nr1 = BB * 256 * 256, nr2 = BB * 128 * 128;
        resize_k<<<cdiv(nr1, 256), 256>>>(S + O_Z, S + O_ZR1, 512, 512, 256, 256, nr1);
        resize_k<<<cdiv(nr2, 256), 256>>>(S + O_Z, S + O_ZR2, 512, 512, 128, 128, nr2);

        for (int s = 0; s < 3; s++) {
            const int hh = 512 >> s, ww = 512 >> s;
            const int hw = hh * ww, n = BB * hw;
            const float* zl = (s == 0) ? (S + O_Z) : ((s == 1) ? (S + O_ZR1) : (S + O_ZR2));

            cudaMemsetAsync(S + O_ACC, 0, sizeof(float) * (size_t)BB * 3 * hw, 0);
            splat_k<<<cdiv(n, 256), 256>>>(fl[s], zl, tvec, dir, S + O_ACC, hh, ww, n);
            norm_k<<<cdiv(n, 256), 256>>>(S + O_ACC, S + O_FLOW, hw, n);

            if (s == 0) {
                backwarp_out_k<<<dim3(cdiv(n, 256), 1), 256>>>(i0,   3,  S + O_FLOW, L0, 70, dir ? 35 : 0, hh, ww, n);
                backwarp_out_k<<<dim3(cdiv(n, 256), 1), 256>>>(fea1, 32, S + O_FLOW, L0, 70, dir ? 38 : 3, hh, ww, n);
            } else if (s == 1) {
                backwarp_out_k<<<dim3(cdiv(n, 256), 2), 256>>>(fea2, 64, S + O_FLOW, L1, 128, dir ? 64 : 0, hh, ww, n);
            } else {
                backwarp_out_k<<<dim3(cdiv(n, 256), 3), 256>>>(fea3, 96, S + O_FLOW, L2, 192, dir ? 96 : 0, hh, ww, n);
            }
        }
    }
}

// round 4
// speedup vs baseline: 1.6078x; 1.0716x over previous
#include <cuda_runtime.h>
#include <cstdint>

// ---------------------------------------------------------------------------
// Problem constants
// ---------------------------------------------------------------------------
#define BB 2
#define H0 512
#define W0 512

// scratch layout (floats)
#define SZ_T1    16777216ull   // 2*32*512*512
#define SZ_FEA1  16777216ull
#define SZ_T2     8388608ull   // 2*64*256*256
#define SZ_FEA2   8388608ull
#define SZ_T3     3145728ull   // 2*96*128*128
#define SZ_FEA3   3145728ull
#define SZ_Z       524288ull   // 2*512*512
#define SZ_ZR1     131072ull
#define SZ_ZR2      32768ull
#define SZ_ACC    1572864ull   // 2*3*512*512
#define SZ_FLOW   1048576ull   // 2*2*512*512

#define O_T1      0ull
#define O_FEA1_0  (O_T1 + SZ_T1)
#define O_FEA1_1  (O_FEA1_0 + SZ_FEA1)
#define O_T2      (O_FEA1_1 + SZ_FEA1)
#define O_FEA2_0  (O_T2 + SZ_T2)
#define O_FEA2_1  (O_FEA2_0 + SZ_FEA2)
#define O_T3      (O_FEA2_1 + SZ_FEA2)
#define O_FEA3_0  (O_T3 + SZ_T3)
#define O_FEA3_1  (O_FEA3_0 + SZ_FEA3)
#define O_Z       (O_FEA3_1 + SZ_FEA3)
#define O_ZR1     (O_Z + SZ_Z)
#define O_ZR2     (O_ZR1 + SZ_ZR1)
#define O_ACC     (O_ZR2 + SZ_ZR2)
#define O_FLOW    (O_ACC + SZ_ACC)
#define SCRATCH_TOTAL (O_FLOW + SZ_FLOW)   // 88,244,224 floats ~ 353 MB

__device__ float g_scratch[SCRATCH_TOTAL];

// ---------------------------------------------------------------------------
// Register-tiled 3x3 conv + PReLU, IC-chunked staging.
//  - Block: 256 threads = 64 pixel-slots x 4 oc-slots. 32 out-channels/block.
//  - Each thread: PX=2 x PY pixels, 8 ocs -> 8*PX*PY accumulators.
//  - Per chunk of CHUNK input channels: stage CHUNK input tiles + CHUNK*288
//    weights behind ONE barrier pair (4x fewer barriers, ~18-deep LDG batch),
//    then run CHUNK x 288 FMAs from registers.
// ---------------------------------------------------------------------------
template <int IC, int STRIDE, int PY, int CHUNK>
__global__ __launch_bounds__(256)
void conv3x3_k(const float* __restrict__ in, const float* __restrict__ wgt,
               const float* __restrict__ bias, const float* __restrict__ prelu_a,
               int aidx, float* __restrict__ out,
               int Hin, int Win, int OC, int ocBlocks)
{
    static_assert(IC % CHUNK == 0, "IC % CHUNK");
    constexpr int PX = 2;
    constexpr int OUT_TW = 16;                 // tile width (pixels)
    constexpr int OUT_TH = 8 * PY;             // tile height
    constexpr int TS_W = OUT_TW * STRIDE + 2;  // input tile W
    constexpr int TS_H = OUT_TH * STRIDE + 2;  // input tile H
    constexpr int TSZ  = TS_W * TS_H;
    constexpr int PW = (PX - 1) * STRIDE + 3;  // per-thread patch W
    constexpr int PH = (PY - 1) * STRIDE + 3;  // per-thread patch H

    __shared__ __align__(16) float s_in[CHUNK * TSZ];
    __shared__ __align__(16) float s_w[CHUNK * 288];

    const int tid = threadIdx.x;
    const int oo  = tid & 3;          // oc slot (8 ocs each)
    const int slot = tid >> 2;        // 64 pixel slots
    const int sx = slot & 7;
    const int sy = slot >> 3;

    const int bz  = blockIdx.z;
    const int ocb = bz % ocBlocks;
    const int b   = bz / ocBlocks;
    const int oc0 = ocb * 32;
    const int Hout = Hin / STRIDE;
    const int Wout = Win / STRIDE;

    const int ox = blockIdx.x * OUT_TW + sx * PX;
    const int oy = blockIdx.y * OUT_TH + sy * PY;
    const int ix0 = blockIdx.x * OUT_TW * STRIDE - 1;
    const int iy0 = blockIdx.y * OUT_TH * STRIDE - 1;

    float acc[8][PX * PY];
#pragma unroll
    for (int o = 0; o < 8; o++)
#pragma unroll
        for (int p = 0; p < PX * PY; p++) acc[o][p] = 0.f;

    const int ly = sy * PY * STRIDE;   // patch origin in s_in
    const int lx = sx * PX * STRIDE;

    for (int cb = 0; cb < IC; cb += CHUNK) {
        __syncthreads();
        // stage CHUNK input planes (batched independent LDGs -> high MLP)
#pragma unroll 4
        for (int i = tid; i < CHUNK * TSZ; i += 256) {
            int c = i / TSZ;
            int j = i - c * TSZ;
            int gy = iy0 + j / TS_W;
            int gx = ix0 + j % TS_W;
            float v = 0.f;
            if (gy >= 0 && gy < Hin && gx >= 0 && gx < Win)
                v = in[((size_t)(b * IC + cb + c)) * Hin * Win + gy * Win + gx];
            s_in[i] = v;
        }
        // stage CHUNK sets of k-major weights: s_w[c][k*32 + oc]
#pragma unroll 2
        for (int i = tid; i < CHUNK * 288; i += 256) {
            int c = i / 288;
            int r = i - c * 288;
            int k = r >> 5, oc = r & 31;
            s_w[i] = wgt[((size_t)(oc0 + oc) * IC + cb + c) * 9 + k];
        }
        __syncthreads();

#pragma unroll
        for (int c = 0; c < CHUNK; c++) {
            float v[PH][PW];
#pragma unroll
            for (int r = 0; r < PH; r++)
#pragma unroll
                for (int cc = 0; cc < PW; cc++)
                    v[r][cc] = s_in[c * TSZ + (ly + r) * TS_W + lx + cc];

#pragma unroll
            for (int k = 0; k < 9; k++) {
                const int ky = k / 3, kx = k % 3;
                const float4 wA = *reinterpret_cast<const float4*>(&s_w[c * 288 + k * 32 + oo * 8]);
                const float4 wB = *reinterpret_cast<const float4*>(&s_w[c * 288 + k * 32 + oo * 8 + 4]);
                const float w8[8] = {wA.x, wA.y, wA.z, wA.w, wB.x, wB.y, wB.z, wB.w};
#pragma unroll
                for (int o = 0; o < 8; o++)
#pragma unroll
                    for (int py = 0; py < PY; py++)
#pragma unroll
                        for (int px = 0; px < PX; px++)
                            acc[o][py * PX + px] =
                                fmaf(v[py * STRIDE + ky][px * STRIDE + kx], w8[o],
                                     acc[o][py * PX + px]);
            }
        }
    }

    const float slope = prelu_a[aidx];
#pragma unroll
    for (int o = 0; o < 8; o++) {
        const int oc = oc0 + oo * 8 + o;
        const float bv = bias[oc];
        float* op = out + (((size_t)b * OC + oc) * Hout) * Wout;
#pragma unroll
        for (int py = 0; py < PY; py++)
#pragma unroll
            for (int px = 0; px < PX; px++) {
                float val = acc[o][py * PX + px] + bv;
                if (val < 0.f) val *= slope;
                op[(size_t)(oy + py) * Wout + ox + px] = val;
            }
    }
}

// ---------------------------------------------------------------------------
// z = param_scale * mean_c |p0 - backwarp(p1, flow)|  (p = 2*img - 1)
// ---------------------------------------------------------------------------
__global__ void z_kernel(const float* __restrict__ i0, const float* __restrict__ i1,
                         const float* __restrict__ flow, const float* __restrict__ pscale,
                         float* __restrict__ z, int h, int w, int n)
{
    int p = blockIdx.x * 256 + threadIdx.x;
    if (p >= n) return;
    const int hw = h * w;
    const int b = p / hw, pp = p % hw;
    const int y = pp / w, x = pp - y * w;

    float f0 = flow[((size_t)b * 2 + 0) * hw + pp];
    float f1 = flow[((size_t)b * 2 + 1) * hw + pp];
    float px = fminf(fmaxf((float)x + f0, 0.f), (float)(w - 1));
    float py = fminf(fmaxf((float)y + f1, 0.f), (float)(h - 1));
    float x0f = floorf(px), y0f = floorf(py);
    int x0 = (int)x0f, y0 = (int)y0f;
    int x1 = min(x0 + 1, w - 1), y1 = min(y0 + 1, h - 1);
    float wx = px - x0f, wy = py - y0f;
    float w00 = (1.f - wx) * (1.f - wy), w10 = wx * (1.f - wy);
    float w01 = (1.f - wx) * wy,        w11 = wx * wy;

    float err = 0.f;
#pragma unroll
    for (int c = 0; c < 3; c++) {
        const float* sp = i1 + ((size_t)(b * 3 + c)) * hw;
        float g = sp[y0 * w + x0] * w00 + sp[y0 * w + x1] * w10 +
                  sp[y1 * w + x0] * w01 + sp[y1 * w + x1] * w11;
        float pg = 2.f * g - 1.f;
        float p0 = 2.f * i0[((size_t)(b * 3 + c)) * hw + pp] - 1.f;
        err += fabsf(p0 - pg);
    }
    err *= (1.f / 3.f);
    z[p] = pscale[0] * err;
}

// ---------------------------------------------------------------------------
// bilinear resize, single channel, exact (i+0.5)*scale - 0.5 coords
// ---------------------------------------------------------------------------
__global__ void resize_k(const float* __restrict__ in, float* __restrict__ out,
                         int hi, int wi, int ho, int wo, int n)
{
    int p = blockIdx.x * 256 + threadIdx.x;
    if (p >= n) return;
    const int hwO = ho * wo;
    const int b = p / hwO, pp = p % hwO;
    const int y = pp / wo, x = pp - y * wo;

    float sy = (float)hi / (float)ho;
    float sx = (float)wi / (float)wo;
    float py = fminf(fmaxf(((float)y + 0.5f) * sy - 0.5f, 0.f), (float)(hi - 1));
    float px = fminf(fmaxf(((float)x + 0.5f) * sx - 0.5f, 0.f), (float)(wi - 1));
    float y0f = floorf(py), x0f = floorf(px);
    int y0 = (int)y0f, x0 = (int)x0f;
    int y1 = min(y0 + 1, hi - 1), x1 = min(x0 + 1, wi - 1);
    float wy = py - y0f, wx = px - x0f;

    const float* sp = in + (size_t)b * hi * wi;
    float r0 = sp[y0 * wi + x0] * (1.f - wx) + sp[y0 * wi + x1] * wx;
    float r1 = sp[y1 * wi + x0] * (1.f - wx) + sp[y1 * wi + x1] * wx;
    out[p] = r0 * (1.f - wy) + r1 * wy;
}

// ---------------------------------------------------------------------------
// softsplat scatter: acc[b, {(-f*ez).x, (-f*ez).y, ez}, h, w] += bilinear
// ---------------------------------------------------------------------------
__global__ void splat_k(const float* __restrict__ flow, const float* __restrict__ zz,
                        const float* __restrict__ tvec, int oneMinus,
                        float* __restrict__ acc, int h, int w, int n)
{
    int p = blockIdx.x * 256 + threadIdx.x;
    if (p >= n) return;
    const int hw = h * w;
    const int b = p / hw, pp = p % hw;
    const int y = pp / w, x = pp - y * w;

    float tt = tvec[b];
    if (oneMinus) tt = 1.f - tt;
    float f0 = tt * flow[((size_t)b * 2 + 0) * hw + pp];
    float f1 = tt * flow[((size_t)b * 2 + 1) * hw + pp];
    float ez = expf(zz[(size_t)b * hw + pp]);
    float v0 = -f0 * ez, v1 = -f1 * ez;

    float fx = (float)x + f0, fy = (float)y + f1;
    float x0f = floorf(fx), y0f = floorf(fy);
    int x0 = (int)x0f, y0 = (int)y0f;
    int x1 = x0 + 1, y1 = y0 + 1;
    float wx1 = fx - x0f, wy1 = fy - y0f;
    float wx0 = 1.f - wx1, wy0 = 1.f - wy1;

    float* a0 = acc + (size_t)b * 3 * hw;
    int cx[4] = {x0, x1, x0, x1};
    int cy[4] = {y0, y0, y1, y1};
    float cw[4] = {wx0 * wy0, wx1 * wy0, wx0 * wy1, wx1 * wy1};
#pragma unroll
    for (int k = 0; k < 4; k++) {
        if (cx[k] >= 0 && cx[k] < w && cy[k] >= 0 && cy[k] < h) {
            int q = cy[k] * w + cx[k];
            float wt = cw[k];
            atomicAdd(a0 + q, v0 * wt);
            atomicAdd(a0 + hw + q, v1 * wt);
            atomicAdd(a0 + 2 * hw + q, ez * wt);
        }
    }
}

__global__ void norm_k(const float* __restrict__ acc, float* __restrict__ flw,
                       int hw, int n)
{
    int p = blockIdx.x * 256 + threadIdx.x;
    if (p >= n) return;
    const int b = p / hw, pp = p % hw;
    float d = acc[((size_t)b * 3 + 2) * hw + pp] + 1e-7f;
    flw[((size_t)b * 2 + 0) * hw + pp] = acc[((size_t)b * 3 + 0) * hw + pp] / d;
    flw[((size_t)b * 2 + 1) * hw + pp] = acc[((size_t)b * 3 + 1) * hw + pp] / d;
}

// ---------------------------------------------------------------------------
// backwarp src (C channels) with flow, write into packed output tensor
// at channel offset c0 within CT total channels. grid.y = channel chunk (8).
// ---------------------------------------------------------------------------
__global__ void backwarp_out_k(const float* __restrict__ src, int C,
                               const float* __restrict__ flow, float* __restrict__ out,
                               int CT, int c0, int h, int w, int n)
{
    int p = blockIdx.x * 256 + threadIdx.x;
    if (p >= n) return;
    const int hw = h * w;
    const int b = p / hw, pp = p % hw;
    const int y = pp / w, x = pp - y * w;

    float f0 = flow[((size_t)b * 2 + 0) * hw + pp];
    float f1 = flow[((size_t)b * 2 + 1) * hw + pp];
    float px = fminf(fmaxf((float)x + f0, 0.f), (float)(w - 1));
    float py = fminf(fmaxf((float)y + f1, 0.f), (float)(h - 1));
    float x0f = floorf(px), y0f = floorf(py);
    int x0 = (int)x0f, y0 = (int)y0f;
    int x1 = min(x0 + 1, w - 1), y1 = min(y0 + 1, h - 1);
    float wx = px - x0f, wy = py - y0f;
    float w00 = (1.f - wx) * (1.f - wy), w10 = wx * (1.f - wy);
    float w01 = (1.f - wx) * wy,        w11 = wx * wy;

    int cbeg = blockIdx.y * 8;
    int cend = min(cbeg + 8, C);
#pragma unroll 4
    for (int c = cbeg; c < cend; c++) {
        const float* sp = src + ((size_t)b * C + c) * hw;
        float g = sp[y0 * w + x0] * w00 + sp[y0 * w + x1] * w10 +
                  sp[y1 * w + x0] * w01 + sp[y1 * w + x1] * w11;
        out[(((size_t)b * CT + c0 + c) * h + y) * w + x] = g;
    }
}

// ---------------------------------------------------------------------------
// Orchestration
// ---------------------------------------------------------------------------
static inline int cdiv(int a, int b) { return (a + b - 1) / b; }

extern "C" void kernel_launch(void* const* d_in, const int* in_sizes, int n_in,
                              void* d_out, int out_size)
{
    const float* in0   = (const float*)d_in[0];
    const float* in1   = (const float*)d_in[1];
    const float* tvec  = (const float*)d_in[2];
    const float* f01[3] = {(const float*)d_in[3], (const float*)d_in[4], (const float*)d_in[5]};
    const float* f10[3] = {(const float*)d_in[6], (const float*)d_in[7], (const float*)d_in[8]};
    const float* W[6]  = {(const float*)d_in[9],  (const float*)d_in[11], (const float*)d_in[13],
                          (const float*)d_in[15], (const float*)d_in[17], (const float*)d_in[19]};
    const float* Bs[6] = {(const float*)d_in[10], (const float*)d_in[12], (const float*)d_in[14],
                          (const float*)d_in[16], (const float*)d_in[18], (const float*)d_in[20]};
    const float* prelu  = (const float*)d_in[21];
    const float* pscale = (const float*)d_in[22];
    float* out = (float*)d_out;

    float* S = nullptr;
    cudaGetSymbolAddress((void**)&S, g_scratch);

    // ---- feature extraction for both images ----
    for (int img = 0; img < 2; img++) {
        const float* x = img ? in1 : in0;
        float* fea1 = S + (img ? O_FEA1_1 : O_FEA1_0);
        float* fea2 = S + (img ? O_FEA2_1 : O_FEA2_0);
        float* fea3 = S + (img ? O_FEA3_1 : O_FEA3_0);

        conv3x3_k<3, 1, 2, 3><<<dim3(32, 32, 2), 256>>>(x,        W[0], Bs[0], prelu, 0, S + O_T1, 512, 512, 32, 1);
        conv3x3_k<32, 1, 2, 4><<<dim3(32, 32, 2), 256>>>(S + O_T1, W[1], Bs[1], prelu, 1, fea1,     512, 512, 32, 1);
        conv3x3_k<32, 2, 1, 4><<<dim3(16, 32, 4), 256>>>(fea1,     W[2], Bs[2], prelu, 2, S + O_T2, 512, 512, 64, 2);
        conv3x3_k<64, 1, 2, 4><<<dim3(16, 16, 4), 256>>>(S + O_T2, W[3], Bs[3], prelu, 3, fea2,     256, 256, 64, 2);
        conv3x3_k<64, 2, 1, 4><<<dim3(8, 16, 6), 256>>>(fea2,      W[4], Bs[4], prelu, 4, S + O_T3, 256, 256, 96, 3);
        conv3x3_k<96, 1, 2, 4><<<dim3(8, 8, 6), 256>>>(S + O_T3,   W[5], Bs[5], prelu, 5, fea3,     128, 128, 96, 3);
    }

    float* L0 = out;                 // (B,70,512,512)
    float* L1 = out + 36700160ull;   // (B,128,256,256)
    float* L2 = out + 53477376ull;   // (B,192,128,128)

    // ---- splat maps, both directions ----
    for (int dir = 0; dir < 2; dir++) {
        const float* i0 = dir ? in1 : in0;
        const float* i1sec = dir ? in0 : in1;
        const float* const* fl = dir ? f10 : f01;
        const float* fea1 = S + (dir ? O_FEA1_1 : O_FEA1_0);
        const float* fea2 = S + (dir ? O_FEA2_1 : O_FEA2_0);
        const float* fea3 = S + (dir ? O_FEA3_1 : O_FEA3_0);

        const int n0 = BB * 512 * 512;
        z_kernel<<<cdiv(n0, 256), 256>>>(i0, i1sec, fl[0], pscale, S + O_Z, 512, 512, n0);
        const int nr1 = BB * 256 * 256, nr2 = BB * 128 * 128;
        resize_k<<<cdiv(nr1, 256), 256>>>(S + O_Z, S + O_ZR1, 512, 512, 256, 256, nr1);
        resize_k<<<cdiv(nr2, 256), 256>>>(S + O_Z, S + O_ZR2, 512, 512, 128, 128, nr2);

        for (int s = 0; s < 3; s++) {
            const int hh = 512 >> s, ww = 512 >> s;
            const int hw = hh * ww, n = BB * hw;
            const float* zl = (s == 0) ? (S + O_Z) : ((s == 1) ? (S + O_ZR1) : (S + O_ZR2));

            cudaMemsetAsync(S + O_ACC, 0, sizeof(float) * (size_t)BB * 3 * hw, 0);
            splat_k<<<cdiv(n, 256), 256>>>(fl[s], zl, tvec, dir, S + O_ACC, hh, ww, n);
            norm_k<<<cdiv(n, 256), 256>>>(S + O_ACC, S + O_FLOW, hw, n);

            if (s == 0) {
                backwarp_out_k<<<dim3(cdiv(n, 256), 1), 256>>>(i0,   3,  S + O_FLOW, L0, 70, dir ? 35 : 0, hh, ww, n);
                backwarp_out_k<<<dim3(cdiv(n, 256), 4), 256>>>(fea1, 32, S + O_FLOW, L0, 70, dir ? 38 : 3, hh, ww, n);
            } else if (s == 1) {
                backwarp_out_k<<<dim3(cdiv(n, 256), 8), 256>>>(fea2, 64, S + O_FLOW, L1, 128, dir ? 64 : 0, hh, ww, n);
            } else {
                backwarp_out_k<<<dim3(cdiv(n, 256), 12), 256>>>(fea3, 96, S + O_FLOW, L2, 192, dir ? 96 : 0, hh, ww, n);
            }
        }
    }
}

// round 5
// speedup vs baseline: 1.6527x; 1.0280x over previous
#include <cuda_runtime.h>
#include <cstdint>

// ---------------------------------------------------------------------------
// Problem constants
// ---------------------------------------------------------------------------
#define BB 2
#define H0 512
#define W0 512

// scratch layout (floats)
#define SZ_T1    16777216ull   // 2*32*512*512
#define SZ_FEA1  16777216ull
#define SZ_T2     8388608ull   // 2*64*256*256
#define SZ_FEA2   8388608ull
#define SZ_T3     3145728ull   // 2*96*128*128
#define SZ_FEA3   3145728ull
#define SZ_Z       524288ull   // 2*512*512
#define SZ_ZR1     131072ull
#define SZ_ZR2      32768ull
#define SZ_ACC    1572864ull   // 2*3*512*512
#define SZ_FLOW   1048576ull   // 2*2*512*512

#define O_T1      0ull
#define O_FEA1_0  (O_T1 + SZ_T1)
#define O_FEA1_1  (O_FEA1_0 + SZ_FEA1)
#define O_T2      (O_FEA1_1 + SZ_FEA1)
#define O_FEA2_0  (O_T2 + SZ_T2)
#define O_FEA2_1  (O_FEA2_0 + SZ_FEA2)
#define O_T3      (O_FEA2_1 + SZ_FEA2)
#define O_FEA3_0  (O_T3 + SZ_T3)
#define O_FEA3_1  (O_FEA3_0 + SZ_FEA3)
#define O_Z       (O_FEA3_1 + SZ_FEA3)
#define O_ZR1     (O_Z + SZ_Z)
#define O_ZR2     (O_ZR1 + SZ_ZR1)
#define O_ACC     (O_ZR2 + SZ_ZR2)
#define O_FLOW    (O_ACC + SZ_ACC)
#define SCRATCH_TOTAL (O_FLOW + SZ_FLOW)   // 88,244,224 floats ~ 353 MB

__device__ float g_scratch[SCRATCH_TOTAL];

// ---------------------------------------------------------------------------
// Register-tiled 3x3 conv + PReLU, IC-chunked staging.
//  - Block: 256 threads = 64 pixel-slots x 4 oc-slots. 32 out-channels/block.
//  - Each thread: PX=2 x PY pixels, 8 ocs -> 8*PX*PY accumulators.
//  - Per chunk of CHUNK input channels: stage CHUNK input tiles + CHUNK*288
//    weights behind ONE barrier pair, then run CHUNK x 72*PY FMAs per thread
//    from registers. Weight LDS (288B/ic) amortized over 2*PY pixels.
// ---------------------------------------------------------------------------
template <int IC, int STRIDE, int PY, int CHUNK>
__global__ __launch_bounds__(256, 2)
void conv3x3_k(const float* __restrict__ in, const float* __restrict__ wgt,
               const float* __restrict__ bias, const float* __restrict__ prelu_a,
               int aidx, float* __restrict__ out,
               int Hin, int Win, int OC, int ocBlocks)
{
    static_assert(IC % CHUNK == 0, "IC % CHUNK");
    constexpr int PX = 2;
    constexpr int OUT_TW = 16;                 // tile width (pixels)
    constexpr int OUT_TH = 8 * PY;             // tile height
    constexpr int TS_W = OUT_TW * STRIDE + 2;  // input tile W
    constexpr int TS_H = OUT_TH * STRIDE + 2;  // input tile H
    constexpr int TSZ  = TS_W * TS_H;
    constexpr int PW = (PX - 1) * STRIDE + 3;  // per-thread patch W
    constexpr int PH = (PY - 1) * STRIDE + 3;  // per-thread patch H

    __shared__ __align__(16) float s_in[CHUNK * TSZ];
    __shared__ __align__(16) float s_w[CHUNK * 288];

    const int tid = threadIdx.x;
    const int oo  = tid & 3;          // oc slot (8 ocs each)
    const int slot = tid >> 2;        // 64 pixel slots
    const int sx = slot & 7;
    const int sy = slot >> 3;

    const int bz  = blockIdx.z;
    const int ocb = bz % ocBlocks;
    const int b   = bz / ocBlocks;
    const int oc0 = ocb * 32;
    const int Hout = Hin / STRIDE;
    const int Wout = Win / STRIDE;

    const int ox = blockIdx.x * OUT_TW + sx * PX;
    const int oy = blockIdx.y * OUT_TH + sy * PY;
    const int ix0 = blockIdx.x * OUT_TW * STRIDE - 1;
    const int iy0 = blockIdx.y * OUT_TH * STRIDE - 1;

    float acc[8][PX * PY];
#pragma unroll
    for (int o = 0; o < 8; o++)
#pragma unroll
        for (int p = 0; p < PX * PY; p++) acc[o][p] = 0.f;

    const int ly = sy * PY * STRIDE;   // patch origin in s_in
    const int lx = sx * PX * STRIDE;

    for (int cb = 0; cb < IC; cb += CHUNK) {
        __syncthreads();
        // stage CHUNK input planes (batched independent LDGs -> high MLP)
#pragma unroll 4
        for (int i = tid; i < CHUNK * TSZ; i += 256) {
            int c = i / TSZ;
            int j = i - c * TSZ;
            int gy = iy0 + j / TS_W;
            int gx = ix0 + j % TS_W;
            float v = 0.f;
            if (gy >= 0 && gy < Hin && gx >= 0 && gx < Win)
                v = in[((size_t)(b * IC + cb + c)) * Hin * Win + gy * Win + gx];
            s_in[i] = v;
        }
        // stage CHUNK sets of k-major weights: s_w[c][k*32 + oc]
#pragma unroll 2
        for (int i = tid; i < CHUNK * 288; i += 256) {
            int c = i / 288;
            int r = i - c * 288;
            int k = r >> 5, oc = r & 31;
            s_w[i] = wgt[((size_t)(oc0 + oc) * IC + cb + c) * 9 + k];
        }
        __syncthreads();

#pragma unroll
        for (int c = 0; c < CHUNK; c++) {
            float v[PH][PW];
#pragma unroll
            for (int r = 0; r < PH; r++)
#pragma unroll
                for (int cc = 0; cc < PW; cc++)
                    v[r][cc] = s_in[c * TSZ + (ly + r) * TS_W + lx + cc];

#pragma unroll
            for (int k = 0; k < 9; k++) {
                const int ky = k / 3, kx = k % 3;
                const float4 wA = *reinterpret_cast<const float4*>(&s_w[c * 288 + k * 32 + oo * 8]);
                const float4 wB = *reinterpret_cast<const float4*>(&s_w[c * 288 + k * 32 + oo * 8 + 4]);
                const float w8[8] = {wA.x, wA.y, wA.z, wA.w, wB.x, wB.y, wB.z, wB.w};
#pragma unroll
                for (int o = 0; o < 8; o++)
#pragma unroll
                    for (int py = 0; py < PY; py++)
#pragma unroll
                        for (int px = 0; px < PX; px++)
                            acc[o][py * PX + px] =
                                fmaf(v[py * STRIDE + ky][px * STRIDE + kx], w8[o],
                                     acc[o][py * PX + px]);
            }
        }
    }

    const float slope = prelu_a[aidx];
#pragma unroll
    for (int o = 0; o < 8; o++) {
        const int oc = oc0 + oo * 8 + o;
        const float bv = bias[oc];
        float* op = out + (((size_t)b * OC + oc) * Hout) * Wout;
#pragma unroll
        for (int py = 0; py < PY; py++)
#pragma unroll
            for (int px = 0; px < PX; px++) {
                float val = acc[o][py * PX + px] + bv;
                if (val < 0.f) val *= slope;
                op[(size_t)(oy + py) * Wout + ox + px] = val;
            }
    }
}

// ---------------------------------------------------------------------------
// z = param_scale * mean_c |p0 - backwarp(p1, flow)|  (p = 2*img - 1)
// ---------------------------------------------------------------------------
__global__ void z_kernel(const float* __restrict__ i0, const float* __restrict__ i1,
                         const float* __restrict__ flow, const float* __restrict__ pscale,
                         float* __restrict__ z, int h, int w, int n)
{
    int p = blockIdx.x * 256 + threadIdx.x;
    if (p >= n) return;
    const int hw = h * w;
    const int b = p / hw, pp = p % hw;
    const int y = pp / w, x = pp - y * w;

    float f0 = flow[((size_t)b * 2 + 0) * hw + pp];
    float f1 = flow[((size_t)b * 2 + 1) * hw + pp];
    float px = fminf(fmaxf((float)x + f0, 0.f), (float)(w - 1));
    float py = fminf(fmaxf((float)y + f1, 0.f), (float)(h - 1));
    float x0f = floorf(px), y0f = floorf(py);
    int x0 = (int)x0f, y0 = (int)y0f;
    int x1 = min(x0 + 1, w - 1), y1 = min(y0 + 1, h - 1);
    float wx = px - x0f, wy = py - y0f;
    float w00 = (1.f - wx) * (1.f - wy), w10 = wx * (1.f - wy);
    float w01 = (1.f - wx) * wy,        w11 = wx * wy;

    float err = 0.f;
#pragma unroll
    for (int c = 0; c < 3; c++) {
        const float* sp = i1 + ((size_t)(b * 3 + c)) * hw;
        float g = sp[y0 * w + x0] * w00 + sp[y0 * w + x1] * w10 +
                  sp[y1 * w + x0] * w01 + sp[y1 * w + x1] * w11;
        float pg = 2.f * g - 1.f;
        float p0 = 2.f * i0[((size_t)(b * 3 + c)) * hw + pp] - 1.f;
        err += fabsf(p0 - pg);
    }
    err *= (1.f / 3.f);
    z[p] = pscale[0] * err;
}

// ---------------------------------------------------------------------------
// bilinear resize, single channel, exact (i+0.5)*scale - 0.5 coords
// ---------------------------------------------------------------------------
__global__ void resize_k(const float* __restrict__ in, float* __restrict__ out,
                         int hi, int wi, int ho, int wo, int n)
{
    int p = blockIdx.x * 256 + threadIdx.x;
    if (p >= n) return;
    const int hwO = ho * wo;
    const int b = p / hwO, pp = p % hwO;
    const int y = pp / wo, x = pp - y * wo;

    float sy = (float)hi / (float)ho;
    float sx = (float)wi / (float)wo;
    float py = fminf(fmaxf(((float)y + 0.5f) * sy - 0.5f, 0.f), (float)(hi - 1));
    float px = fminf(fmaxf(((float)x + 0.5f) * sx - 0.5f, 0.f), (float)(wi - 1));
    float y0f = floorf(py), x0f = floorf(px);
    int y0 = (int)y0f, x0 = (int)x0f;
    int y1 = min(y0 + 1, hi - 1), x1 = min(x0 + 1, wi - 1);
    float wy = py - y0f, wx = px - x0f;

    const float* sp = in + (size_t)b * hi * wi;
    float r0 = sp[y0 * wi + x0] * (1.f - wx) + sp[y0 * wi + x1] * wx;
    float r1 = sp[y1 * wi + x0] * (1.f - wx) + sp[y1 * wi + x1] * wx;
    out[p] = r0 * (1.f - wy) + r1 * wy;
}

// ---------------------------------------------------------------------------
// softsplat scatter: acc[b, {(-f*ez).x, (-f*ez).y, ez}, h, w] += bilinear
// ---------------------------------------------------------------------------
__global__ void splat_k(const float* __restrict__ flow, const float* __restrict__ zz,
                        const float* __restrict__ tvec, int oneMinus,
                        float* __restrict__ acc, int h, int w, int n)
{
    int p = blockIdx.x * 256 + threadIdx.x;
    if (p >= n) return;
    const int hw = h * w;
    const int b = p / hw, pp = p % hw;
    const int y = pp / w, x = pp - y * w;

    float tt = tvec[b];
    if (oneMinus) tt = 1.f - tt;
    float f0 = tt * flow[((size_t)b * 2 + 0) * hw + pp];
    float f1 = tt * flow[((size_t)b * 2 + 1) * hw + pp];
    float ez = expf(zz[(size_t)b * hw + pp]);
    float v0 = -f0 * ez, v1 = -f1 * ez;

    float fx = (float)x + f0, fy = (float)y + f1;
    float x0f = floorf(fx), y0f = floorf(fy);
    int x0 = (int)x0f, y0 = (int)y0f;
    int x1 = x0 + 1, y1 = y0 + 1;
    float wx1 = fx - x0f, wy1 = fy - y0f;
    float wx0 = 1.f - wx1, wy0 = 1.f - wy1;

    float* a0 = acc + (size_t)b * 3 * hw;
    int cx[4] = {x0, x1, x0, x1};
    int cy[4] = {y0, y0, y1, y1};
    float cw[4] = {wx0 * wy0, wx1 * wy0, wx0 * wy1, wx1 * wy1};
#pragma unroll
    for (int k = 0; k < 4; k++) {
        if (cx[k] >= 0 && cx[k] < w && cy[k] >= 0 && cy[k] < h) {
            int q = cy[k] * w + cx[k];
            float wt = cw[k];
            atomicAdd(a0 + q, v0 * wt);
            atomicAdd(a0 + hw + q, v1 * wt);
            atomicAdd(a0 + 2 * hw + q, ez * wt);
        }
    }
}

__global__ void norm_k(const float* __restrict__ acc, float* __restrict__ flw,
                       int hw, int n)
{
    int p = blockIdx.x * 256 + threadIdx.x;
    if (p >= n) return;
    const int b = p / hw, pp = p % hw;
    float d = acc[((size_t)b * 3 + 2) * hw + pp] + 1e-7f;
    flw[((size_t)b * 2 + 0) * hw + pp] = acc[((size_t)b * 3 + 0) * hw + pp] / d;
    flw[((size_t)b * 2 + 1) * hw + pp] = acc[((size_t)b * 3 + 1) * hw + pp] / d;
}

// ---------------------------------------------------------------------------
// backwarp src (C channels) with flow, write into packed output tensor
// at channel offset c0 within CT total channels. grid.y = channel chunk (8).
// ---------------------------------------------------------------------------
__global__ void backwarp_out_k(const float* __restrict__ src, int C,
                               const float* __restrict__ flow, float* __restrict__ out,
                               int CT, int c0, int h, int w, int n)
{
    int p = blockIdx.x * 256 + threadIdx.x;
    if (p >= n) return;
    const int hw = h * w;
    const int b = p / hw, pp = p % hw;
    const int y = pp / w, x = pp - y * w;

    float f0 = flow[((size_t)b * 2 + 0) * hw + pp];
    float f1 = flow[((size_t)b * 2 + 1) * hw + pp];
    float px = fminf(fmaxf((float)x + f0, 0.f), (float)(w - 1));
    float py = fminf(fmaxf((float)y + f1, 0.f), (float)(h - 1));
    float x0f = floorf(px), y0f = floorf(py);
    int x0 = (int)x0f, y0 = (int)y0f;
    int x1 = min(x0 + 1, w - 1), y1 = min(y0 + 1, h - 1);
    float wx = px - x0f, wy = py - y0f;
    float w00 = (1.f - wx) * (1.f - wy), w10 = wx * (1.f - wy);
    float w01 = (1.f - wx) * wy,        w11 = wx * wy;

    int cbeg = blockIdx.y * 8;
    int cend = min(cbeg + 8, C);
#pragma unroll 4
    for (int c = cbeg; c < cend; c++) {
        const float* sp = src + ((size_t)b * C + c) * hw;
        float g = sp[y0 * w + x0] * w00 + sp[y0 * w + x1] * w10 +
                  sp[y1 * w + x0] * w01 + sp[y1 * w + x1] * w11;
        out[(((size_t)b * CT + c0 + c) * h + y) * w + x] = g;
    }
}

// ---------------------------------------------------------------------------
// Orchestration
// ---------------------------------------------------------------------------
static inline int cdiv(int a, int b) { return (a + b - 1) / b; }

extern "C" void kernel_launch(void* const* d_in, const int* in_sizes, int n_in,
                              void* d_out, int out_size)
{
    const float* in0   = (const float*)d_in[0];
    const float* in1   = (const float*)d_in[1];
    const float* tvec  = (const float*)d_in[2];
    const float* f01[3] = {(const float*)d_in[3], (const float*)d_in[4], (const float*)d_in[5]};
    const float* f10[3] = {(const float*)d_in[6], (const float*)d_in[7], (const float*)d_in[8]};
    const float* W[6]  = {(const float*)d_in[9],  (const float*)d_in[11], (const float*)d_in[13],
                          (const float*)d_in[15], (const float*)d_in[17], (const float*)d_in[19]};
    const float* Bs[6] = {(const float*)d_in[10], (const float*)d_in[12], (const float*)d_in[14],
                          (const float*)d_in[16], (const float*)d_in[18], (const float*)d_in[20]};
    const float* prelu  = (const float*)d_in[21];
    const float* pscale = (const float*)d_in[22];
    float* out = (float*)d_out;

    float* S = nullptr;
    cudaGetSymbolAddress((void**)&S, g_scratch);

    // ---- feature extraction for both images ----
    // stride1 layers: 16x32 output tile (PY=4, 8 px/thread);
    // stride2 layers: 16x16 output tile (PY=2, 4 px/thread).
    for (int img = 0; img < 2; img++) {
        const float* x = img ? in1 : in0;
        float* fea1 = S + (img ? O_FEA1_1 : O_FEA1_0);
        float* fea2 = S + (img ? O_FEA2_1 : O_FEA2_0);
        float* fea3 = S + (img ? O_FEA3_1 : O_FEA3_0);

        conv3x3_k<3, 1, 4, 3><<<dim3(32, 16, 2), 256>>>(x,        W[0], Bs[0], prelu, 0, S + O_T1, 512, 512, 32, 1);
        conv3x3_k<32, 1, 4, 4><<<dim3(32, 16, 2), 256>>>(S + O_T1, W[1], Bs[1], prelu, 1, fea1,     512, 512, 32, 1);
        conv3x3_k<32, 2, 2, 4><<<dim3(16, 16, 4), 256>>>(fea1,     W[2], Bs[2], prelu, 2, S + O_T2, 512, 512, 64, 2);
        conv3x3_k<64, 1, 4, 4><<<dim3(16, 8, 4), 256>>>(S + O_T2,  W[3], Bs[3], prelu, 3, fea2,     256, 256, 64, 2);
        conv3x3_k<64, 2, 2, 4><<<dim3(8, 8, 6), 256>>>(fea2,       W[4], Bs[4], prelu, 4, S + O_T3, 256, 256, 96, 3);
        conv3x3_k<96, 1, 4, 4><<<dim3(8, 4, 6), 256>>>(S + O_T3,   W[5], Bs[5], prelu, 5, fea3,     128, 128, 96, 3);
    }

    float* L0 = out;                 // (B,70,512,512)
    float* L1 = out + 36700160ull;   // (B,128,256,256)
    float* L2 = out + 53477376ull;   // (B,192,128,128)

    // ---- splat maps, both directions ----
    for (int dir = 0; dir < 2; dir++) {
        const float* i0 = dir ? in1 : in0;
        const float* i1sec = dir ? in0 : in1;
        const float* const* fl = dir ? f10 : f01;
        const float* fea1 = S + (dir ? O_FEA1_1 : O_FEA1_0);
        const float* fea2 = S + (dir ? O_FEA2_1 : O_FEA2_0);
        const float* fea3 = S + (dir ? O_FEA3_1 : O_FEA3_0);

        const int n0 = BB * 512 * 512;
        z_kernel<<<cdiv(n0, 256), 256>>>(i0, i1sec, fl[0], pscale, S + O_Z, 512, 512, n0);
        const int nr1 = BB * 256 * 256, nr2 = BB * 128 * 128;
        resize_k<<<cdiv(nr1, 256), 256>>>(S + O_Z, S + O_ZR1, 512, 512, 256, 256, nr1);
        resize_k<<<cdiv(nr2, 256), 256>>>(S + O_Z, S + O_ZR2, 512, 512, 128, 128, nr2);

        for (int s = 0; s < 3; s++) {
            const int hh = 512 >> s, ww = 512 >> s;
            const int hw = hh * ww, n = BB * hw;
            const float* zl = (s == 0) ? (S + O_Z) : ((s == 1) ? (S + O_ZR1) : (S + O_ZR2));

            cudaMemsetAsync(S + O_ACC, 0, sizeof(float) * (size_t)BB * 3 * hw, 0);
            splat_k<<<cdiv(n, 256), 256>>>(fl[s], zl, tvec, dir, S + O_ACC, hh, ww, n);
            norm_k<<<cdiv(n, 256), 256>>>(S + O_ACC, S + O_FLOW, hw, n);

            if (s == 0) {
                backwarp_out_k<<<dim3(cdiv(n, 256), 1), 256>>>(i0,   3,  S + O_FLOW, L0, 70, dir ? 35 : 0, hh, ww, n);
                backwarp_out_k<<<dim3(cdiv(n, 256), 4), 256>>>(fea1, 32, S + O_FLOW, L0, 70, dir ? 38 : 3, hh, ww, n);
            } else if (s == 1) {
                backwarp_out_k<<<dim3(cdiv(n, 256), 8), 256>>>(fea2, 64, S + O_FLOW, L1, 128, dir ? 64 : 0, hh, ww, n);
            } else {
                backwarp_out_k<<<dim3(cdiv(n, 256), 12), 256>>>(fea3, 96, S + O_FLOW, L2, 192, dir ? 96 : 0, hh, ww, n);
            }
        }
    }
}

// round 6
// speedup vs baseline: 1.7669x; 1.0691x over previous
#include <cuda_runtime.h>
#include <cstdint>

// ---------------------------------------------------------------------------
// Problem constants
// ---------------------------------------------------------------------------
#define BB 2
#define H0 512
#define W0 512

// scratch layout (floats)
#define SZ_T1    16777216ull   // 2*32*512*512
#define SZ_FEA1  16777216ull
#define SZ_T2     8388608ull   // 2*64*256*256
#define SZ_FEA2   8388608ull
#define SZ_T3     3145728ull   // 2*96*128*128
#define SZ_FEA3   3145728ull
#define SZ_Z       524288ull   // 2*512*512
#define SZ_ZR1     131072ull
#define SZ_ZR2      32768ull
#define SZ_ACC    1572864ull   // 2*3*512*512
#define SZ_FLOW   1048576ull   // 2*2*512*512

#define O_T1      0ull
#define O_FEA1_0  (O_T1 + SZ_T1)
#define O_FEA1_1  (O_FEA1_0 + SZ_FEA1)
#define O_T2      (O_FEA1_1 + SZ_FEA1)
#define O_FEA2_0  (O_T2 + SZ_T2)
#define O_FEA2_1  (O_FEA2_0 + SZ_FEA2)
#define O_T3      (O_FEA2_1 + SZ_FEA2)
#define O_FEA3_0  (O_T3 + SZ_T3)
#define O_FEA3_1  (O_FEA3_0 + SZ_FEA3)
#define O_Z       (O_FEA3_1 + SZ_FEA3)
#define O_ZR1     (O_Z + SZ_Z)
#define O_ZR2     (O_ZR1 + SZ_ZR1)
#define O_ACC     (O_ZR2 + SZ_ZR2)
#define O_FLOW    (O_ACC + SZ_ACC)
#define SCRATCH_TOTAL (O_FLOW + SZ_FLOW)   // 88,244,224 floats ~ 353 MB

__device__ float g_scratch[SCRATCH_TOTAL];

// ---------------------------------------------------------------------------
// cp.async helpers (4B, with zero-fill predicate via src-size operand)
// ---------------------------------------------------------------------------
__device__ __forceinline__ void cp_async4(uint32_t smem_dst, const void* gsrc, bool pred)
{
    int sz = pred ? 4 : 0;
    asm volatile("cp.async.ca.shared.global [%0], [%1], 4, %2;\n"
                 :: "r"(smem_dst), "l"(gsrc), "r"(sz));
}
__device__ __forceinline__ void cp_commit() { asm volatile("cp.async.commit_group;\n"); }
template <int N>
__device__ __forceinline__ void cp_wait() { asm volatile("cp.async.wait_group %0;\n" :: "n"(N)); }

// ---------------------------------------------------------------------------
// Register-tiled 3x3 conv + PReLU, IC-chunked, double-buffered cp.async.
//  - Block: 256 threads = 64 pixel-slots x 4 oc-slots. 32 out-channels/block.
//  - Each thread: PX=2 x PY pixels, 8 ocs.
//  - Chunk i+1 staged via cp.async while chunk i computes (2 smem buffers).
// ---------------------------------------------------------------------------
template <int IC, int STRIDE, int PY, int CHUNK>
__global__ __launch_bounds__(256, 2)
void conv3x3_k(const float* __restrict__ in, const float* __restrict__ wgt,
               const float* __restrict__ bias, const float* __restrict__ prelu_a,
               int aidx, float* __restrict__ out,
               int Hin, int Win, int OC, int ocBlocks)
{
    static_assert(IC % CHUNK == 0, "IC % CHUNK");
    constexpr int PX = 2;
    constexpr int OUT_TW = 16;
    constexpr int OUT_TH = 8 * PY;
    constexpr int TS_W = OUT_TW * STRIDE + 2;
    constexpr int TS_H = OUT_TH * STRIDE + 2;
    constexpr int TSZ  = TS_W * TS_H;
    constexpr int PW = (PX - 1) * STRIDE + 3;
    constexpr int PH = (PY - 1) * STRIDE + 3;
    constexpr int NCH = IC / CHUNK;           // number of chunks
    constexpr int BUF = CHUNK * TSZ + CHUNK * 288;   // floats per buffer

    __shared__ __align__(16) float s_mem[2 * BUF];

    const int tid = threadIdx.x;
    const int oo  = tid & 3;
    const int slot = tid >> 2;
    const int sx = slot & 7;
    const int sy = slot >> 3;

    const int bz  = blockIdx.z;
    const int ocb = bz % ocBlocks;
    const int b   = bz / ocBlocks;
    const int oc0 = ocb * 32;
    const int Hout = Hin / STRIDE;
    const int Wout = Win / STRIDE;

    const int ox = blockIdx.x * OUT_TW + sx * PX;
    const int oy = blockIdx.y * OUT_TH + sy * PY;
    const int ix0 = blockIdx.x * OUT_TW * STRIDE - 1;
    const int iy0 = blockIdx.y * OUT_TH * STRIDE - 1;

    const int ly = sy * PY * STRIDE;
    const int lx = sx * PX * STRIDE;

    // ---- staging lambda: stage chunk 'ci' (ic base = ci*CHUNK) into buffer ----
    auto stage = [&](int ci, int bufIdx) {
        float* sb = s_mem + bufIdx * BUF;
        const uint32_t s_in_a = (uint32_t)__cvta_generic_to_shared(sb);
        const uint32_t s_w_a  = (uint32_t)__cvta_generic_to_shared(sb + CHUNK * TSZ);
        const int cb = ci * CHUNK;
#pragma unroll 4
        for (int i = tid; i < CHUNK * TSZ; i += 256) {
            int c = i / TSZ;
            int j = i - c * TSZ;
            int gy = iy0 + j / TS_W;
            int gx = ix0 + j % TS_W;
            bool ok = (gy >= 0 && gy < Hin && gx >= 0 && gx < Win);
            const float* src = in + ((size_t)(b * IC + cb + c)) * Hin * Win
                                  + (ok ? (gy * Win + gx) : 0);
            cp_async4(s_in_a + 4u * i, src, ok);
        }
#pragma unroll 2
        for (int i = tid; i < CHUNK * 288; i += 256) {
            int c = i / 288;
            int r = i - c * 288;
            int k = r >> 5, oc = r & 31;
            cp_async4(s_w_a + 4u * i,
                      &wgt[((size_t)(oc0 + oc) * IC + cb + c) * 9 + k], true);
        }
        cp_commit();
    };

    float acc[8][PX * PY];
#pragma unroll
    for (int o = 0; o < 8; o++)
#pragma unroll
        for (int p = 0; p < PX * PY; p++) acc[o][p] = 0.f;

    stage(0, 0);

    for (int ci = 0; ci < NCH; ci++) {
        const int cur = ci & 1;
        if (ci + 1 < NCH) stage(ci + 1, cur ^ 1);

        if (ci + 1 < NCH) cp_wait<1>(); else cp_wait<0>();
        __syncthreads();

        const float* s_in = s_mem + cur * BUF;
        const float* s_w  = s_in + CHUNK * TSZ;

#pragma unroll
        for (int c = 0; c < CHUNK; c++) {
            float v[PH][PW];
#pragma unroll
            for (int r = 0; r < PH; r++)
#pragma unroll
                for (int cc = 0; cc < PW; cc++)
                    v[r][cc] = s_in[c * TSZ + (ly + r) * TS_W + lx + cc];

#pragma unroll
            for (int k = 0; k < 9; k++) {
                const int ky = k / 3, kx = k % 3;
                const float4 wA = *reinterpret_cast<const float4*>(&s_w[c * 288 + k * 32 + oo * 8]);
                const float4 wB = *reinterpret_cast<const float4*>(&s_w[c * 288 + k * 32 + oo * 8 + 4]);
                const float w8[8] = {wA.x, wA.y, wA.z, wA.w, wB.x, wB.y, wB.z, wB.w};
#pragma unroll
                for (int o = 0; o < 8; o++)
#pragma unroll
                    for (int py = 0; py < PY; py++)
#pragma unroll
                        for (int px = 0; px < PX; px++)
                            acc[o][py * PX + px] =
                                fmaf(v[py * STRIDE + ky][px * STRIDE + kx], w8[o],
                                     acc[o][py * PX + px]);
            }
        }
        __syncthreads();
    }

    const float slope = prelu_a[aidx];
#pragma unroll
    for (int o = 0; o < 8; o++) {
        const int oc = oc0 + oo * 8 + o;
        const float bv = bias[oc];
        float* op = out + (((size_t)b * OC + oc) * Hout) * Wout;
#pragma unroll
        for (int py = 0; py < PY; py++)
#pragma unroll
            for (int px = 0; px < PX; px++) {
                float val = acc[o][py * PX + px] + bv;
                if (val < 0.f) val *= slope;
                op[(size_t)(oy + py) * Wout + ox + px] = val;
            }
    }
}

// ---------------------------------------------------------------------------
// z = param_scale * mean_c |p0 - backwarp(p1, flow)|  (p = 2*img - 1)
// ---------------------------------------------------------------------------
__global__ void z_kernel(const float* __restrict__ i0, const float* __restrict__ i1,
                         const float* __restrict__ flow, const float* __restrict__ pscale,
                         float* __restrict__ z, int h, int w, int n)
{
    int p = blockIdx.x * 256 + threadIdx.x;
    if (p >= n) return;
    const int hw = h * w;
    const int b = p / hw, pp = p % hw;
    const int y = pp / w, x = pp - y * w;

    float f0 = flow[((size_t)b * 2 + 0) * hw + pp];
    float f1 = flow[((size_t)b * 2 + 1) * hw + pp];
    float px = fminf(fmaxf((float)x + f0, 0.f), (float)(w - 1));
    float py = fminf(fmaxf((float)y + f1, 0.f), (float)(h - 1));
    float x0f = floorf(px), y0f = floorf(py);
    int x0 = (int)x0f, y0 = (int)y0f;
    int x1 = min(x0 + 1, w - 1), y1 = min(y0 + 1, h - 1);
    float wx = px - x0f, wy = py - y0f;
    float w00 = (1.f - wx) * (1.f - wy), w10 = wx * (1.f - wy);
    float w01 = (1.f - wx) * wy,        w11 = wx * wy;

    float err = 0.f;
#pragma unroll
    for (int c = 0; c < 3; c++) {
        const float* sp = i1 + ((size_t)(b * 3 + c)) * hw;
        float g = sp[y0 * w + x0] * w00 + sp[y0 * w + x1] * w10 +
                  sp[y1 * w + x0] * w01 + sp[y1 * w + x1] * w11;
        float pg = 2.f * g - 1.f;
        float p0 = 2.f * i0[((size_t)(b * 3 + c)) * hw + pp] - 1.f;
        err += fabsf(p0 - pg);
    }
    err *= (1.f / 3.f);
    z[p] = pscale[0] * err;
}

// ---------------------------------------------------------------------------
// bilinear resize, single channel, exact (i+0.5)*scale - 0.5 coords
// ---------------------------------------------------------------------------
__global__ void resize_k(const float* __restrict__ in, float* __restrict__ out,
                         int hi, int wi, int ho, int wo, int n)
{
    int p = blockIdx.x * 256 + threadIdx.x;
    if (p >= n) return;
    const int hwO = ho * wo;
    const int b = p / hwO, pp = p % hwO;
    const int y = pp / wo, x = pp - y * wo;

    float sy = (float)hi / (float)ho;
    float sx = (float)wi / (float)wo;
    float py = fminf(fmaxf(((float)y + 0.5f) * sy - 0.5f, 0.f), (float)(hi - 1));
    float px = fminf(fmaxf(((float)x + 0.5f) * sx - 0.5f, 0.f), (float)(wi - 1));
    float y0f = floorf(py), x0f = floorf(px);
    int y0 = (int)y0f, x0 = (int)x0f;
    int y1 = min(y0 + 1, hi - 1), x1 = min(x0 + 1, wi - 1);
    float wy = py - y0f, wx = px - x0f;

    const float* sp = in + (size_t)b * hi * wi;
    float r0 = sp[y0 * wi + x0] * (1.f - wx) + sp[y0 * wi + x1] * wx;
    float r1 = sp[y1 * wi + x0] * (1.f - wx) + sp[y1 * wi + x1] * wx;
    out[p] = r0 * (1.f - wy) + r1 * wy;
}

// ---------------------------------------------------------------------------
// softsplat scatter: acc[b, {(-f*ez).x, (-f*ez).y, ez}, h, w] += bilinear
// ---------------------------------------------------------------------------
__global__ void splat_k(const float* __restrict__ flow, const float* __restrict__ zz,
                        const float* __restrict__ tvec, int oneMinus,
                        float* __restrict__ acc, int h, int w, int n)
{
    int p = blockIdx.x * 256 + threadIdx.x;
    if (p >= n) return;
    const int hw = h * w;
    const int b = p / hw, pp = p % hw;
    const int y = pp / w, x = pp - y * w;

    float tt = tvec[b];
    if (oneMinus) tt = 1.f - tt;
    float f0 = tt * flow[((size_t)b * 2 + 0) * hw + pp];
    float f1 = tt * flow[((size_t)b * 2 + 1) * hw + pp];
    float ez = expf(zz[(size_t)b * hw + pp]);
    float v0 = -f0 * ez, v1 = -f1 * ez;

    float fx = (float)x + f0, fy = (float)y + f1;
    float x0f = floorf(fx), y0f = floorf(fy);
    int x0 = (int)x0f, y0 = (int)y0f;
    int x1 = x0 + 1, y1 = y0 + 1;
    float wx1 = fx - x0f, wy1 = fy - y0f;
    float wx0 = 1.f - wx1, wy0 = 1.f - wy1;

    float* a0 = acc + (size_t)b * 3 * hw;
    int cx[4] = {x0, x1, x0, x1};
    int cy[4] = {y0, y0, y1, y1};
    float cw[4] = {wx0 * wy0, wx1 * wy0, wx0 * wy1, wx1 * wy1};
#pragma unroll
    for (int k = 0; k < 4; k++) {
        if (cx[k] >= 0 && cx[k] < w && cy[k] >= 0 && cy[k] < h) {
            int q = cy[k] * w + cx[k];
            float wt = cw[k];
            atomicAdd(a0 + q, v0 * wt);
            atomicAdd(a0 + hw + q, v1 * wt);
            atomicAdd(a0 + 2 * hw + q, ez * wt);
        }
    }
}

__global__ void norm_k(const float* __restrict__ acc, float* __restrict__ flw,
                       int hw, int n)
{
    int p = blockIdx.x * 256 + threadIdx.x;
    if (p >= n) return;
    const int b = p / hw, pp = p % hw;
    float d = acc[((size_t)b * 3 + 2) * hw + pp] + 1e-7f;
    flw[((size_t)b * 2 + 0) * hw + pp] = acc[((size_t)b * 3 + 0) * hw + pp] / d;
    flw[((size_t)b * 2 + 1) * hw + pp] = acc[((size_t)b * 3 + 1) * hw + pp] / d;
}

// ---------------------------------------------------------------------------
// backwarp src (C channels) with flow, write into packed output tensor
// at channel offset c0 within CT total channels. grid.y = channel chunk (8).
// ---------------------------------------------------------------------------
__global__ void backwarp_out_k(const float* __restrict__ src, int C,
                               const float* __restrict__ flow, float* __restrict__ out,
                               int CT, int c0, int h, int w, int n)
{
    int p = blockIdx.x * 256 + threadIdx.x;
    if (p >= n) return;
    const int hw = h * w;
    const int b = p / hw, pp = p % hw;
    const int y = pp / w, x = pp - y * w;

    float f0 = flow[((size_t)b * 2 + 0) * hw + pp];
    float f1 = flow[((size_t)b * 2 + 1) * hw + pp];
    float px = fminf(fmaxf((float)x + f0, 0.f), (float)(w - 1));
    float py = fminf(fmaxf((float)y + f1, 0.f), (float)(h - 1));
    float x0f = floorf(px), y0f = floorf(py);
    int x0 = (int)x0f, y0 = (int)y0f;
    int x1 = min(x0 + 1, w - 1), y1 = min(y0 + 1, h - 1);
    float wx = px - x0f, wy = py - y0f;
    float w00 = (1.f - wx) * (1.f - wy), w10 = wx * (1.f - wy);
    float w01 = (1.f - wx) * wy,        w11 = wx * wy;

    int cbeg = blockIdx.y * 8;
    int cend = min(cbeg + 8, C);
#pragma unroll 4
    for (int c = cbeg; c < cend; c++) {
        const float* sp = src + ((size_t)b * C + c) * hw;
        float g = sp[y0 * w + x0] * w00 + sp[y0 * w + x1] * w10 +
                  sp[y1 * w + x0] * w01 + sp[y1 * w + x1] * w11;
        out[(((size_t)b * CT + c0 + c) * h + y) * w + x] = g;
    }
}

// ---------------------------------------------------------------------------
// Orchestration
// ---------------------------------------------------------------------------
static inline int cdiv(int a, int b) { return (a + b - 1) / b; }

extern "C" void kernel_launch(void* const* d_in, const int* in_sizes, int n_in,
                              void* d_out, int out_size)
{
    const float* in0   = (const float*)d_in[0];
    const float* in1   = (const float*)d_in[1];
    const float* tvec  = (const float*)d_in[2];
    const float* f01[3] = {(const float*)d_in[3], (const float*)d_in[4], (const float*)d_in[5]};
    const float* f10[3] = {(const float*)d_in[6], (const float*)d_in[7], (const float*)d_in[8]};
    const float* W[6]  = {(const float*)d_in[9],  (const float*)d_in[11], (const float*)d_in[13],
                          (const float*)d_in[15], (const float*)d_in[17], (const float*)d_in[19]};
    const float* Bs[6] = {(const float*)d_in[10], (const float*)d_in[12], (const float*)d_in[14],
                          (const float*)d_in[16], (const float*)d_in[18], (const float*)d_in[20]};
    const float* prelu  = (const float*)d_in[21];
    const float* pscale = (const float*)d_in[22];
    float* out = (float*)d_out;

    float* S = nullptr;
    cudaGetSymbolAddress((void**)&S, g_scratch);

    // ---- feature extraction for both images ----
    for (int img = 0; img < 2; img++) {
        const float* x = img ? in1 : in0;
        float* fea1 = S + (img ? O_FEA1_1 : O_FEA1_0);
        float* fea2 = S + (img ? O_FEA2_1 : O_FEA2_0);
        float* fea3 = S + (img ? O_FEA3_1 : O_FEA3_0);

        conv3x3_k<3, 1, 4, 3><<<dim3(32, 16, 2), 256>>>(x,        W[0], Bs[0], prelu, 0, S + O_T1, 512, 512, 32, 1);
        conv3x3_k<32, 1, 4, 4><<<dim3(32, 16, 2), 256>>>(S + O_T1, W[1], Bs[1], prelu, 1, fea1,     512, 512, 32, 1);
        conv3x3_k<32, 2, 2, 4><<<dim3(16, 16, 4), 256>>>(fea1,     W[2], Bs[2], prelu, 2, S + O_T2, 512, 512, 64, 2);
        conv3x3_k<64, 1, 4, 4><<<dim3(16, 8, 4), 256>>>(S + O_T2,  W[3], Bs[3], prelu, 3, fea2,     256, 256, 64, 2);
        conv3x3_k<64, 2, 2, 4><<<dim3(8, 8, 6), 256>>>(fea2,       W[4], Bs[4], prelu, 4, S + O_T3, 256, 256, 96, 3);
        conv3x3_k<96, 1, 4, 4><<<dim3(8, 4, 6), 256>>>(S + O_T3,   W[5], Bs[5], prelu, 5, fea3,     128, 128, 96, 3);
    }

    float* L0 = out;                 // (B,70,512,512)
    float* L1 = out + 36700160ull;   // (B,128,256,256)
    float* L2 = out + 53477376ull;   // (B,192,128,128)

    // ---- splat maps, both directions ----
    for (int dir = 0; dir < 2; dir++) {
        const float* i0 = dir ? in1 : in0;
        const float* i1sec = dir ? in0 : in1;
        const float* const* fl = dir ? f10 : f01;
        const float* fea1 = S + (dir ? O_FEA1_1 : O_FEA1_0);
        const float* fea2 = S + (dir ? O_FEA2_1 : O_FEA2_0);
        const float* fea3 = S + (dir ? O_FEA3_1 : O_FEA3_0);

        const int n0 = BB * 512 * 512;
        z_kernel<<<cdiv(n0, 256), 256>>>(i0, i1sec, fl[0], pscale, S + O_Z, 512, 512, n0);
        const int nr1 = BB * 256 * 256, nr2 = BB * 128 * 128;
        resize_k<<<cdiv(nr1, 256), 256>>>(S + O_Z, S + O_ZR1, 512, 512, 256, 256, nr1);
        resize_k<<<cdiv(nr2, 256), 256>>>(S + O_Z, S + O_ZR2, 512, 512, 128, 128, nr2);

        for (int s = 0; s < 3; s++) {
            const int hh = 512 >> s, ww = 512 >> s;
            const int hw = hh * ww, n = BB * hw;
            const float* zl = (s == 0) ? (S + O_Z) : ((s == 1) ? (S + O_ZR1) : (S + O_ZR2));

            cudaMemsetAsync(S + O_ACC, 0, sizeof(float) * (size_t)BB * 3 * hw, 0);
            splat_k<<<cdiv(n, 256), 256>>>(fl[s], zl, tvec, dir, S + O_ACC, hh, ww, n);
            norm_k<<<cdiv(n, 256), 256>>>(S + O_ACC, S + O_FLOW, hw, n);

            if (s == 0) {
                backwarp_out_k<<<dim3(cdiv(n, 256), 1), 256>>>(i0,   3,  S + O_FLOW, L0, 70, dir ? 35 : 0, hh, ww, n);
                backwarp_out_k<<<dim3(cdiv(n, 256), 4), 256>>>(fea1, 32, S + O_FLOW, L0, 70, dir ? 38 : 3, hh, ww, n);
            } else if (s == 1) {
                backwarp_out_k<<<dim3(cdiv(n, 256), 8), 256>>>(fea2, 64, S + O_FLOW, L1, 128, dir ? 64 : 0, hh, ww, n);
            } else {
                backwarp_out_k<<<dim3(cdiv(n, 256), 12), 256>>>(fea3, 96, S + O_FLOW, L2, 192, dir ? 96 : 0, hh, ww, n);
            }
        }
    }
}

// round 7
// speedup vs baseline: 1.7714x; 1.0025x over previous
#include <cuda_runtime.h>
#include <cstdint>

// ---------------------------------------------------------------------------
// Problem constants
// ---------------------------------------------------------------------------
#define BB 2
#define H0 512
#define W0 512

// scratch layout (floats)
#define SZ_T1    16777216ull   // 2*32*512*512
#define SZ_FEA1  16777216ull
#define SZ_T2     8388608ull   // 2*64*256*256
#define SZ_FEA2   8388608ull
#define SZ_T3     3145728ull   // 2*96*128*128
#define SZ_FEA3   3145728ull
#define SZ_Z       524288ull   // 2*512*512
#define SZ_ZR1     131072ull
#define SZ_ZR2      32768ull
#define SZ_ACC    1572864ull   // 2*3*512*512
#define SZ_FLOW   1048576ull   // 2*2*512*512

#define O_T1      0ull
#define O_FEA1_0  (O_T1 + SZ_T1)
#define O_FEA1_1  (O_FEA1_0 + SZ_FEA1)
#define O_T2      (O_FEA1_1 + SZ_FEA1)
#define O_FEA2_0  (O_T2 + SZ_T2)
#define O_FEA2_1  (O_FEA2_0 + SZ_FEA2)
#define O_T3      (O_FEA2_1 + SZ_FEA2)
#define O_FEA3_0  (O_T3 + SZ_T3)
#define O_FEA3_1  (O_FEA3_0 + SZ_FEA3)
#define O_Z       (O_FEA3_1 + SZ_FEA3)
#define O_ZR1     (O_Z + SZ_Z)
#define O_ZR2     (O_ZR1 + SZ_ZR1)
#define O_ACC     (O_ZR2 + SZ_ZR2)
#define O_FLOW    (O_ACC + SZ_ACC)
#define SCRATCH_TOTAL (O_FLOW + SZ_FLOW)   // 88,244,224 floats ~ 353 MB

__device__ float g_scratch[SCRATCH_TOTAL];

// ---------------------------------------------------------------------------
// packed f32x2 helpers (sm_103a): 1 instruction = 2 fp32 FMAs
// ---------------------------------------------------------------------------
__device__ __forceinline__ unsigned long long ffma2(unsigned long long a,
                                                    unsigned long long b,
                                                    unsigned long long c)
{
    unsigned long long d;
    asm("fma.rn.f32x2 %0, %1, %2, %3;" : "=l"(d) : "l"(a), "l"(b), "l"(c));
    return d;
}
__device__ __forceinline__ unsigned long long pack2(float lo, float hi)
{
    unsigned long long d;
    asm("mov.b64 %0, {%1, %2};" : "=l"(d) : "r"(__float_as_uint(lo)), "r"(__float_as_uint(hi)));
    return d;
}
__device__ __forceinline__ void unpack2(unsigned long long v, float& lo, float& hi)
{
    unsigned int a, b2;
    asm("mov.b64 {%0, %1}, %2;" : "=r"(a), "=r"(b2) : "l"(v));
    lo = __uint_as_float(a);
    hi = __uint_as_float(b2);
}

// ---------------------------------------------------------------------------
// cp.async helpers (4B, with zero-fill predicate via src-size operand)
// ---------------------------------------------------------------------------
__device__ __forceinline__ void cp_async4(uint32_t smem_dst, const void* gsrc, bool pred)
{
    int sz = pred ? 4 : 0;
    asm volatile("cp.async.ca.shared.global [%0], [%1], 4, %2;\n"
                 :: "r"(smem_dst), "l"(gsrc), "r"(sz));
}
__device__ __forceinline__ void cp_commit() { asm volatile("cp.async.commit_group;\n"); }
template <int N>
__device__ __forceinline__ void cp_wait() { asm volatile("cp.async.wait_group %0;\n" :: "n"(N)); }

// ---------------------------------------------------------------------------
// Register-tiled 3x3 conv + PReLU, IC-chunked, double-buffered cp.async,
// inner loop in packed f32x2 (px dimension packed, 2 FMAs/instr).
// ---------------------------------------------------------------------------
template <int IC, int STRIDE, int PY, int CHUNK>
__global__ __launch_bounds__(256, 2)
void conv3x3_k(const float* __restrict__ in, const float* __restrict__ wgt,
               const float* __restrict__ bias, const float* __restrict__ prelu_a,
               int aidx, float* __restrict__ out,
               int Hin, int Win, int OC, int ocBlocks)
{
    static_assert(IC % CHUNK == 0, "IC % CHUNK");
    constexpr int PX = 2;
    constexpr int OUT_TW = 16;
    constexpr int OUT_TH = 8 * PY;
    constexpr int TS_W = OUT_TW * STRIDE + 2;
    constexpr int TS_H = OUT_TH * STRIDE + 2;
    constexpr int TSZ  = TS_W * TS_H;
    constexpr int PW = (PX - 1) * STRIDE + 3;
    constexpr int PH = (PY - 1) * STRIDE + 3;
    constexpr int NCH = IC / CHUNK;
    constexpr int BUF = CHUNK * TSZ + CHUNK * 288;

    __shared__ __align__(16) float s_mem[2 * BUF];

    const int tid = threadIdx.x;
    const int oo  = tid & 3;
    const int slot = tid >> 2;
    const int sx = slot & 7;
    const int sy = slot >> 3;

    const int bz  = blockIdx.z;
    const int ocb = bz % ocBlocks;
    const int b   = bz / ocBlocks;
    const int oc0 = ocb * 32;
    const int Hout = Hin / STRIDE;
    const int Wout = Win / STRIDE;

    const int ox = blockIdx.x * OUT_TW + sx * PX;
    const int oy = blockIdx.y * OUT_TH + sy * PY;
    const int ix0 = blockIdx.x * OUT_TW * STRIDE - 1;
    const int iy0 = blockIdx.y * OUT_TH * STRIDE - 1;

    const int ly = sy * PY * STRIDE;
    const int lx = sx * PX * STRIDE;

    auto stage = [&](int ci, int bufIdx) {
        float* sb = s_mem + bufIdx * BUF;
        const uint32_t s_in_a = (uint32_t)__cvta_generic_to_shared(sb);
        const uint32_t s_w_a  = (uint32_t)__cvta_generic_to_shared(sb + CHUNK * TSZ);
        const int cb = ci * CHUNK;
#pragma unroll 4
        for (int i = tid; i < CHUNK * TSZ; i += 256) {
            int c = i / TSZ;
            int j = i - c * TSZ;
            int gy = iy0 + j / TS_W;
            int gx = ix0 + j % TS_W;
            bool ok = (gy >= 0 && gy < Hin && gx >= 0 && gx < Win);
            const float* src = in + ((size_t)(b * IC + cb + c)) * Hin * Win
                                  + (ok ? (gy * Win + gx) : 0);
            cp_async4(s_in_a + 4u * i, src, ok);
        }
#pragma unroll 2
        for (int i = tid; i < CHUNK * 288; i += 256) {
            int c = i / 288;
            int r = i - c * 288;
            int k = r >> 5, oc = r & 31;
            cp_async4(s_w_a + 4u * i,
                      &wgt[((size_t)(oc0 + oc) * IC + cb + c) * 9 + k], true);
        }
        cp_commit();
    };

    // packed accumulators: acc2[o][py] holds (px=0, px=1)
    unsigned long long acc2[8][PY];
#pragma unroll
    for (int o = 0; o < 8; o++)
#pragma unroll
        for (int p = 0; p < PY; p++) acc2[o][p] = 0ull;

    stage(0, 0);

    for (int ci = 0; ci < NCH; ci++) {
        const int cur = ci & 1;
        if (ci + 1 < NCH) stage(ci + 1, cur ^ 1);

        if (ci + 1 < NCH) cp_wait<1>(); else cp_wait<0>();
        __syncthreads();

        const float* s_in = s_mem + cur * BUF;
        const float* s_w  = s_in + CHUNK * TSZ;

#pragma unroll
        for (int c = 0; c < CHUNK; c++) {
            float v[PH][PW];
#pragma unroll
            for (int r = 0; r < PH; r++)
#pragma unroll
                for (int cc = 0; cc < PW; cc++)
                    v[r][cc] = s_in[c * TSZ + (ly + r) * TS_W + lx + cc];

#pragma unroll
            for (int k = 0; k < 9; k++) {
                const int ky = k / 3, kx = k % 3;
                const float4 wA = *reinterpret_cast<const float4*>(&s_w[c * 288 + k * 32 + oo * 8]);
                const float4 wB = *reinterpret_cast<const float4*>(&s_w[c * 288 + k * 32 + oo * 8 + 4]);
                unsigned long long pw[8];
                pw[0] = pack2(wA.x, wA.x); pw[1] = pack2(wA.y, wA.y);
                pw[2] = pack2(wA.z, wA.z); pw[3] = pack2(wA.w, wA.w);
                pw[4] = pack2(wB.x, wB.x); pw[5] = pack2(wB.y, wB.y);
                pw[6] = pack2(wB.z, wB.z); pw[7] = pack2(wB.w, wB.w);
#pragma unroll
                for (int py = 0; py < PY; py++) {
                    const unsigned long long pvv =
                        pack2(v[py * STRIDE + ky][kx], v[py * STRIDE + ky][kx + STRIDE]);
#pragma unroll
                    for (int o = 0; o < 8; o++)
                        acc2[o][py] = ffma2(pvv, pw[o], acc2[o][py]);
                }
            }
        }
        __syncthreads();
    }

    const float slope = prelu_a[aidx];
#pragma unroll
    for (int o = 0; o < 8; o++) {
        const int oc = oc0 + oo * 8 + o;
        const float bv = bias[oc];
        float* op = out + (((size_t)b * OC + oc) * Hout) * Wout;
#pragma unroll
        for (int py = 0; py < PY; py++) {
            float v0, v1;
            unpack2(acc2[o][py], v0, v1);
            v0 += bv; if (v0 < 0.f) v0 *= slope;
            v1 += bv; if (v1 < 0.f) v1 *= slope;
            *reinterpret_cast<float2*>(&op[(size_t)(oy + py) * Wout + ox]) =
                make_float2(v0, v1);
        }
    }
}

// ---------------------------------------------------------------------------
// z = param_scale * mean_c |p0 - backwarp(p1, flow)|  (p = 2*img - 1)
// ---------------------------------------------------------------------------
__global__ void z_kernel(const float* __restrict__ i0, const float* __restrict__ i1,
                         const float* __restrict__ flow, const float* __restrict__ pscale,
                         float* __restrict__ z, int h, int w, int n)
{
    int p = blockIdx.x * 256 + threadIdx.x;
    if (p >= n) return;
    const int hw = h * w;
    const int b = p / hw, pp = p % hw;
    const int y = pp / w, x = pp - y * w;

    float f0 = flow[((size_t)b * 2 + 0) * hw + pp];
    float f1 = flow[((size_t)b * 2 + 1) * hw + pp];
    float px = fminf(fmaxf((float)x + f0, 0.f), (float)(w - 1));
    float py = fminf(fmaxf((float)y + f1, 0.f), (float)(h - 1));
    float x0f = floorf(px), y0f = floorf(py);
    int x0 = (int)x0f, y0 = (int)y0f;
    int x1 = min(x0 + 1, w - 1), y1 = min(y0 + 1, h - 1);
    float wx = px - x0f, wy = py - y0f;
    float w00 = (1.f - wx) * (1.f - wy), w10 = wx * (1.f - wy);
    float w01 = (1.f - wx) * wy,        w11 = wx * wy;

    float err = 0.f;
#pragma unroll
    for (int c = 0; c < 3; c++) {
        const float* sp = i1 + ((size_t)(b * 3 + c)) * hw;
        float g = sp[y0 * w + x0] * w00 + sp[y0 * w + x1] * w10 +
                  sp[y1 * w + x0] * w01 + sp[y1 * w + x1] * w11;
        float pg = 2.f * g - 1.f;
        float p0 = 2.f * i0[((size_t)(b * 3 + c)) * hw + pp] - 1.f;
        err += fabsf(p0 - pg);
    }
    err *= (1.f / 3.f);
    z[p] = pscale[0] * err;
}

// ---------------------------------------------------------------------------
// bilinear resize, single channel, exact (i+0.5)*scale - 0.5 coords
// ---------------------------------------------------------------------------
__global__ void resize_k(const float* __restrict__ in, float* __restrict__ out,
                         int hi, int wi, int ho, int wo, int n)
{
    int p = blockIdx.x * 256 + threadIdx.x;
    if (p >= n) return;
    const int hwO = ho * wo;
    const int b = p / hwO, pp = p % hwO;
    const int y = pp / wo, x = pp - y * wo;

    float sy = (float)hi / (float)ho;
    float sx = (float)wi / (float)wo;
    float py = fminf(fmaxf(((float)y + 0.5f) * sy - 0.5f, 0.f), (float)(hi - 1));
    float px = fminf(fmaxf(((float)x + 0.5f) * sx - 0.5f, 0.f), (float)(wi - 1));
    float y0f = floorf(py), x0f = floorf(px);
    int y0 = (int)y0f, x0 = (int)x0f;
    int y1 = min(y0 + 1, hi - 1), x1 = min(x0 + 1, wi - 1);
    float wy = py - y0f, wx = px - x0f;

    const float* sp = in + (size_t)b * hi * wi;
    float r0 = sp[y0 * wi + x0] * (1.f - wx) + sp[y0 * wi + x1] * wx;
    float r1 = sp[y1 * wi + x0] * (1.f - wx) + sp[y1 * wi + x1] * wx;
    out[p] = r0 * (1.f - wy) + r1 * wy;
}

// ---------------------------------------------------------------------------
// softsplat scatter: acc[b, {(-f*ez).x, (-f*ez).y, ez}, h, w] += bilinear
// ---------------------------------------------------------------------------
__global__ void splat_k(const float* __restrict__ flow, const float* __restrict__ zz,
                        const float* __restrict__ tvec, int oneMinus,
                        float* __restrict__ acc, int h, int w, int n)
{
    int p = blockIdx.x * 256 + threadIdx.x;
    if (p >= n) return;
    const int hw = h * w;
    const int b = p / hw, pp = p % hw;
    const int y = pp / w, x = pp - y * w;

    float tt = tvec[b];
    if (oneMinus) tt = 1.f - tt;
    float f0 = tt * flow[((size_t)b * 2 + 0) * hw + pp];
    float f1 = tt * flow[((size_t)b * 2 + 1) * hw + pp];
    float ez = expf(zz[(size_t)b * hw + pp]);
    float v0 = -f0 * ez, v1 = -f1 * ez;

    float fx = (float)x + f0, fy = (float)y + f1;
    float x0f = floorf(fx), y0f = floorf(fy);
    int x0 = (int)x0f, y0 = (int)y0f;
    int x1 = x0 + 1, y1 = y0 + 1;
    float wx1 = fx - x0f, wy1 = fy - y0f;
    float wx0 = 1.f - wx1, wy0 = 1.f - wy1;

    float* a0 = acc + (size_t)b * 3 * hw;
    int cx[4] = {x0, x1, x0, x1};
    int cy[4] = {y0, y0, y1, y1};
    float cw[4] = {wx0 * wy0, wx1 * wy0, wx0 * wy1, wx1 * wy1};
#pragma unroll
    for (int k = 0; k < 4; k++) {
        if (cx[k] >= 0 && cx[k] < w && cy[k] >= 0 && cy[k] < h) {
            int q = cy[k] * w + cx[k];
            float wt = cw[k];
            atomicAdd(a0 + q, v0 * wt);
            atomicAdd(a0 + hw + q, v1 * wt);
            atomicAdd(a0 + 2 * hw + q, ez * wt);
        }
    }
}

__global__ void norm_k(const float* __restrict__ acc, float* __restrict__ flw,
                       int hw, int n)
{
    int p = blockIdx.x * 256 + threadIdx.x;
    if (p >= n) return;
    const int b = p / hw, pp = p % hw;
    float d = acc[((size_t)b * 3 + 2) * hw + pp] + 1e-7f;
    flw[((size_t)b * 2 + 0) * hw + pp] = acc[((size_t)b * 3 + 0) * hw + pp] / d;
    flw[((size_t)b * 2 + 1) * hw + pp] = acc[((size_t)b * 3 + 1) * hw + pp] / d;
}

// ---------------------------------------------------------------------------
// backwarp src (C channels) with flow, write into packed output tensor
// at channel offset c0 within CT total channels. grid.y = channel chunk (8).
// ---------------------------------------------------------------------------
__global__ void backwarp_out_k(const float* __restrict__ src, int C,
                               const float* __restrict__ flow, float* __restrict__ out,
                               int CT, int c0, int h, int w, int n)
{
    int p = blockIdx.x * 256 + threadIdx.x;
    if (p >= n) return;
    const int hw = h * w;
    const int b = p / hw, pp = p % hw;
    const int y = pp / w, x = pp - y * w;

    float f0 = flow[((size_t)b * 2 + 0) * hw + pp];
    float f1 = flow[((size_t)b * 2 + 1) * hw + pp];
    float px = fminf(fmaxf((float)x + f0, 0.f), (float)(w - 1));
    float py = fminf(fmaxf((float)y + f1, 0.f), (float)(h - 1));
    float x0f = floorf(px), y0f = floorf(py);
    int x0 = (int)x0f, y0 = (int)y0f;
    int x1 = min(x0 + 1, w - 1), y1 = min(y0 + 1, h - 1);
    float wx = px - x0f, wy = py - y0f;
    float w00 = (1.f - wx) * (1.f - wy), w10 = wx * (1.f - wy);
    float w01 = (1.f - wx) * wy,        w11 = wx * wy;

    int cbeg = blockIdx.y * 8;
    int cend = min(cbeg + 8, C);
#pragma unroll 4
    for (int c = cbeg; c < cend; c++) {
        const float* sp = src + ((size_t)b * C + c) * hw;
        float g = sp[y0 * w + x0] * w00 + sp[y0 * w + x1] * w10 +
                  sp[y1 * w + x0] * w01 + sp[y1 * w + x1] * w11;
        out[(((size_t)b * CT + c0 + c) * h + y) * w + x] = g;
    }
}

// ---------------------------------------------------------------------------
// Orchestration
// ---------------------------------------------------------------------------
static inline int cdiv(int a, int b) { return (a + b - 1) / b; }

extern "C" void kernel_launch(void* const* d_in, const int* in_sizes, int n_in,
                              void* d_out, int out_size)
{
    const float* in0   = (const float*)d_in[0];
    const float* in1   = (const float*)d_in[1];
    const float* tvec  = (const float*)d_in[2];
    const float* f01[3] = {(const float*)d_in[3], (const float*)d_in[4], (const float*)d_in[5]};
    const float* f10[3] = {(const float*)d_in[6], (const float*)d_in[7], (const float*)d_in[8]};
    const float* W[6]  = {(const float*)d_in[9],  (const float*)d_in[11], (const float*)d_in[13],
                          (const float*)d_in[15], (const float*)d_in[17], (const float*)d_in[19]};
    const float* Bs[6] = {(const float*)d_in[10], (const float*)d_in[12], (const float*)d_in[14],
                          (const float*)d_in[16], (const float*)d_in[18], (const float*)d_in[20]};
    const float* prelu  = (const float*)d_in[21];
    const float* pscale = (const float*)d_in[22];
    float* out = (float*)d_out;

    float* S = nullptr;
    cudaGetSymbolAddress((void**)&S, g_scratch);

    // ---- feature extraction for both images ----
    for (int img = 0; img < 2; img++) {
        const float* x = img ? in1 : in0;
        float* fea1 = S + (img ? O_FEA1_1 : O_FEA1_0);
        float* fea2 = S + (img ? O_FEA2_1 : O_FEA2_0);
        float* fea3 = S + (img ? O_FEA3_1 : O_FEA3_0);

        conv3x3_k<3, 1, 4, 3><<<dim3(32, 16, 2), 256>>>(x,        W[0], Bs[0], prelu, 0, S + O_T1, 512, 512, 32, 1);
        conv3x3_k<32, 1, 4, 4><<<dim3(32, 16, 2), 256>>>(S + O_T1, W[1], Bs[1], prelu, 1, fea1,     512, 512, 32, 1);
        conv3x3_k<32, 2, 2, 4><<<dim3(16, 16, 4), 256>>>(fea1,     W[2], Bs[2], prelu, 2, S + O_T2, 512, 512, 64, 2);
        conv3x3_k<64, 1, 4, 4><<<dim3(16, 8, 4), 256>>>(S + O_T2,  W[3], Bs[3], prelu, 3, fea2,     256, 256, 64, 2);
        conv3x3_k<64, 2, 2, 4><<<dim3(8, 8, 6), 256>>>(fea2,       W[4], Bs[4], prelu, 4, S + O_T3, 256, 256, 96, 3);
        conv3x3_k<96, 1, 4, 4><<<dim3(8, 4, 6), 256>>>(S + O_T3,   W[5], Bs[5], prelu, 5, fea3,     128, 128, 96, 3);
    }

    float* L0 = out;                 // (B,70,512,512)
    float* L1 = out + 36700160ull;   // (B,128,256,256)
    float* L2 = out + 53477376ull;   // (B,192,128,128)

    // ---- splat maps, both directions ----
    for (int dir = 0; dir < 2; dir++) {
        const float* i0 = dir ? in1 : in0;
        const float* i1sec = dir ? in0 : in1;
        const float* const* fl = dir ? f10 : f01;
        const float* fea1 = S + (dir ? O_FEA1_1 : O_FEA1_0);
        const float* fea2 = S + (dir ? O_FEA2_1 : O_FEA2_0);
        const float* fea3 = S + (dir ? O_FEA3_1 : O_FEA3_0);

        const int n0 = BB * 512 * 512;
        z_kernel<<<cdiv(n0, 256), 256>>>(i0, i1sec, fl[0], pscale, S + O_Z, 512, 512, n0);
        const int nr1 = BB * 256 * 256, nr2 = BB * 128 * 128;
        resize_k<<<cdiv(nr1, 256), 256>>>(S + O_Z, S + O_ZR1, 512, 512, 256, 256, nr1);
        resize_k<<<cdiv(nr2, 256), 256>>>(S + O_Z, S + O_ZR2, 512, 512, 128, 128, nr2);

        for (int s = 0; s < 3; s++) {
            const int hh = 512 >> s, ww = 512 >> s;
            const int hw = hh * ww, n = BB * hw;
            const float* zl = (s == 0) ? (S + O_Z) : ((s == 1) ? (S + O_ZR1) : (S + O_ZR2));

            cudaMemsetAsync(S + O_ACC, 0, sizeof(float) * (size_t)BB * 3 * hw, 0);
            splat_k<<<cdiv(n, 256), 256>>>(fl[s], zl, tvec, dir, S + O_ACC, hh, ww, n);
            norm_k<<<cdiv(n, 256), 256>>>(S + O_ACC, S + O_FLOW, hw, n);

            if (s == 0) {
                backwarp_out_k<<<dim3(cdiv(n, 256), 1), 256>>>(i0,   3,  S + O_FLOW, L0, 70, dir ? 35 : 0, hh, ww, n);
                backwarp_out_k<<<dim3(cdiv(n, 256), 4), 256>>>(fea1, 32, S + O_FLOW, L0, 70, dir ? 38 : 3, hh, ww, n);
            } else if (s == 1) {
                backwarp_out_k<<<dim3(cdiv(n, 256), 8), 256>>>(fea2, 64, S + O_FLOW, L1, 128, dir ? 64 : 0, hh, ww, n);
            } else {
                backwarp_out_k<<<dim3(cdiv(n, 256), 12), 256>>>(fea3, 96, S + O_FLOW, L2, 192, dir ? 96 : 0, hh, ww, n);
            }
        }
    }
}

// round 8
// speedup vs baseline: 1.7902x; 1.0106x over previous
#include <cuda_runtime.h>
#include <cstdint>

// ---------------------------------------------------------------------------
// Problem constants
// ---------------------------------------------------------------------------
#define BB 2
#define H0 512
#define W0 512

// scratch layout (floats)
#define SZ_T1    16777216ull   // 2*32*512*512
#define SZ_FEA1  16777216ull
#define SZ_T2     8388608ull   // 2*64*256*256
#define SZ_FEA2   8388608ull
#define SZ_T3     3145728ull   // 2*96*128*128
#define SZ_FEA3   3145728ull
#define SZ_Z       524288ull   // 2*512*512
#define SZ_ZR1     131072ull
#define SZ_ZR2      32768ull
#define SZ_ACC    1572864ull   // 2*3*512*512
#define SZ_FLOW   1048576ull   // 2*2*512*512

#define O_T1      0ull
#define O_FEA1_0  (O_T1 + SZ_T1)
#define O_FEA1_1  (O_FEA1_0 + SZ_FEA1)
#define O_T2      (O_FEA1_1 + SZ_FEA1)
#define O_FEA2_0  (O_T2 + SZ_T2)
#define O_FEA2_1  (O_FEA2_0 + SZ_FEA2)
#define O_T3      (O_FEA2_1 + SZ_FEA2)
#define O_FEA3_0  (O_T3 + SZ_T3)
#define O_FEA3_1  (O_FEA3_0 + SZ_FEA3)
#define O_Z       (O_FEA3_1 + SZ_FEA3)
#define O_ZR1     (O_Z + SZ_Z)
#define O_ZR2     (O_ZR1 + SZ_ZR1)
#define O_ACC     (O_ZR2 + SZ_ZR2)
#define O_FLOW    (O_ACC + SZ_ACC)
#define SCRATCH_TOTAL (O_FLOW + SZ_FLOW)   // 88,244,224 floats ~ 353 MB

__device__ float g_scratch[SCRATCH_TOTAL];

// ---------------------------------------------------------------------------
// cp.async helpers (4B, with zero-fill predicate via src-size operand)
// ---------------------------------------------------------------------------
__device__ __forceinline__ void cp_async4(uint32_t smem_dst, const void* gsrc, bool pred)
{
    int sz = pred ? 4 : 0;
    asm volatile("cp.async.ca.shared.global [%0], [%1], 4, %2;\n"
                 :: "r"(smem_dst), "l"(gsrc), "r"(sz));
}
__device__ __forceinline__ void cp_commit() { asm volatile("cp.async.commit_group;\n"); }
template <int N>
__device__ __forceinline__ void cp_wait() { asm volatile("cp.async.wait_group %0;\n" :: "n"(N)); }

// ---------------------------------------------------------------------------
// Register-tiled 3x3 conv + PReLU, IC-chunked, double-buffered cp.async,
// scalar FFMA inner loop (R6 form; FFMA2 reverted — no throughput on sm_103a).
// Dynamic smem: big CHUNK (8) halves barrier count vs R6.
// ---------------------------------------------------------------------------
template <int IC, int STRIDE, int PY, int CHUNK>
__global__ __launch_bounds__(256, 2)
void conv3x3_k(const float* __restrict__ in, const float* __restrict__ wgt,
               const float* __restrict__ bias, const float* __restrict__ prelu_a,
               int aidx, float* __restrict__ out,
               int Hin, int Win, int OC, int ocBlocks)
{
    static_assert(IC % CHUNK == 0, "IC % CHUNK");
    constexpr int PX = 2;
    constexpr int OUT_TW = 16;
    constexpr int OUT_TH = 8 * PY;
    constexpr int TS_W = OUT_TW * STRIDE + 2;
    constexpr int TS_H = OUT_TH * STRIDE + 2;
    constexpr int TSZ  = TS_W * TS_H;
    constexpr int PW = (PX - 1) * STRIDE + 3;
    constexpr int PH = (PY - 1) * STRIDE + 3;
    constexpr int NCH = IC / CHUNK;
    constexpr int BUF = CHUNK * TSZ + CHUNK * 288;

    extern __shared__ __align__(16) float s_mem[];   // 2 * BUF floats

    const int tid = threadIdx.x;
    const int oo  = tid & 3;
    const int slot = tid >> 2;
    const int sx = slot & 7;
    const int sy = slot >> 3;

    const int bz  = blockIdx.z;
    const int ocb = bz % ocBlocks;
    const int b   = bz / ocBlocks;
    const int oc0 = ocb * 32;
    const int Hout = Hin / STRIDE;
    const int Wout = Win / STRIDE;

    const int ox = blockIdx.x * OUT_TW + sx * PX;
    const int oy = blockIdx.y * OUT_TH + sy * PY;
    const int ix0 = blockIdx.x * OUT_TW * STRIDE - 1;
    const int iy0 = blockIdx.y * OUT_TH * STRIDE - 1;

    const int ly = sy * PY * STRIDE;
    const int lx = sx * PX * STRIDE;

    auto stage = [&](int ci, int bufIdx) {
        float* sb = s_mem + bufIdx * BUF;
        const uint32_t s_in_a = (uint32_t)__cvta_generic_to_shared(sb);
        const uint32_t s_w_a  = (uint32_t)__cvta_generic_to_shared(sb + CHUNK * TSZ);
        const int cb = ci * CHUNK;
#pragma unroll 4
        for (int i = tid; i < CHUNK * TSZ; i += 256) {
            int c = i / TSZ;
            int j = i - c * TSZ;
            int gy = iy0 + j / TS_W;
            int gx = ix0 + j % TS_W;
            bool ok = (gy >= 0 && gy < Hin && gx >= 0 && gx < Win);
            const float* src = in + ((size_t)(b * IC + cb + c)) * Hin * Win
                                  + (ok ? (gy * Win + gx) : 0);
            cp_async4(s_in_a + 4u * i, src, ok);
        }
#pragma unroll 4
        for (int i = tid; i < CHUNK * 288; i += 256) {
            int c = i / 288;
            int r = i - c * 288;
            int k = r >> 5, oc = r & 31;
            cp_async4(s_w_a + 4u * i,
                      &wgt[((size_t)(oc0 + oc) * IC + cb + c) * 9 + k], true);
        }
        cp_commit();
    };

    float acc[8][PX * PY];
#pragma unroll
    for (int o = 0; o < 8; o++)
#pragma unroll
        for (int p = 0; p < PX * PY; p++) acc[o][p] = 0.f;

    stage(0, 0);

    for (int ci = 0; ci < NCH; ci++) {
        const int cur = ci & 1;
        if (ci + 1 < NCH) stage(ci + 1, cur ^ 1);

        if (ci + 1 < NCH) cp_wait<1>(); else cp_wait<0>();
        __syncthreads();

        const float* s_in = s_mem + cur * BUF;
        const float* s_w  = s_in + CHUNK * TSZ;

#pragma unroll
        for (int c = 0; c < CHUNK; c++) {
            float v[PH][PW];
#pragma unroll
            for (int r = 0; r < PH; r++)
#pragma unroll
                for (int cc = 0; cc < PW; cc++)
                    v[r][cc] = s_in[c * TSZ + (ly + r) * TS_W + lx + cc];

#pragma unroll
            for (int k = 0; k < 9; k++) {
                const int ky = k / 3, kx = k % 3;
                const float4 wA = *reinterpret_cast<const float4*>(&s_w[c * 288 + k * 32 + oo * 8]);
                const float4 wB = *reinterpret_cast<const float4*>(&s_w[c * 288 + k * 32 + oo * 8 + 4]);
                const float w8[8] = {wA.x, wA.y, wA.z, wA.w, wB.x, wB.y, wB.z, wB.w};
#pragma unroll
                for (int o = 0; o < 8; o++)
#pragma unroll
                    for (int py = 0; py < PY; py++)
#pragma unroll
                        for (int px = 0; px < PX; px++)
                            acc[o][py * PX + px] =
                                fmaf(v[py * STRIDE + ky][px * STRIDE + kx], w8[o],
                                     acc[o][py * PX + px]);
            }
        }
        __syncthreads();
    }

    const float slope = prelu_a[aidx];
#pragma unroll
    for (int o = 0; o < 8; o++) {
        const int oc = oc0 + oo * 8 + o;
        const float bv = bias[oc];
        float* op = out + (((size_t)b * OC + oc) * Hout) * Wout;
#pragma unroll
        for (int py = 0; py < PY; py++) {
            float v0 = acc[o][py * PX + 0] + bv;
            float v1 = acc[o][py * PX + 1] + bv;
            if (v0 < 0.f) v0 *= slope;
            if (v1 < 0.f) v1 *= slope;
            *reinterpret_cast<float2*>(&op[(size_t)(oy + py) * Wout + ox]) =
                make_float2(v0, v1);
        }
    }
}

// ---------------------------------------------------------------------------
// z = param_scale * mean_c |p0 - backwarp(p1, flow)|  (p = 2*img - 1)
// ---------------------------------------------------------------------------
__global__ void z_kernel(const float* __restrict__ i0, const float* __restrict__ i1,
                         const float* __restrict__ flow, const float* __restrict__ pscale,
                         float* __restrict__ z, int h, int w, int n)
{
    int p = blockIdx.x * 256 + threadIdx.x;
    if (p >= n) return;
    const int hw = h * w;
    const int b = p / hw, pp = p % hw;
    const int y = pp / w, x = pp - y * w;

    float f0 = flow[((size_t)b * 2 + 0) * hw + pp];
    float f1 = flow[((size_t)b * 2 + 1) * hw + pp];
    float px = fminf(fmaxf((float)x + f0, 0.f), (float)(w - 1));
    float py = fminf(fmaxf((float)y + f1, 0.f), (float)(h - 1));
    float x0f = floorf(px), y0f = floorf(py);
    int x0 = (int)x0f, y0 = (int)y0f;
    int x1 = min(x0 + 1, w - 1), y1 = min(y0 + 1, h - 1);
    float wx = px - x0f, wy = py - y0f;
    float w00 = (1.f - wx) * (1.f - wy), w10 = wx * (1.f - wy);
    float w01 = (1.f - wx) * wy,        w11 = wx * wy;

    float err = 0.f;
#pragma unroll
    for (int c = 0; c < 3; c++) {
        const float* sp = i1 + ((size_t)(b * 3 + c)) * hw;
        float g = sp[y0 * w + x0] * w00 + sp[y0 * w + x1] * w10 +
                  sp[y1 * w + x0] * w01 + sp[y1 * w + x1] * w11;
        float pg = 2.f * g - 1.f;
        float p0 = 2.f * i0[((size_t)(b * 3 + c)) * hw + pp] - 1.f;
        err += fabsf(p0 - pg);
    }
    err *= (1.f / 3.f);
    z[p] = pscale[0] * err;
}

// ---------------------------------------------------------------------------
// bilinear resize, single channel, exact (i+0.5)*scale - 0.5 coords
// ---------------------------------------------------------------------------
__global__ void resize_k(const float* __restrict__ in, float* __restrict__ out,
                         int hi, int wi, int ho, int wo, int n)
{
    int p = blockIdx.x * 256 + threadIdx.x;
    if (p >= n) return;
    const int hwO = ho * wo;
    const int b = p / hwO, pp = p % hwO;
    const int y = pp / wo, x = pp - y * wo;

    float sy = (float)hi / (float)ho;
    float sx = (float)wi / (float)wo;
    float py = fminf(fmaxf(((float)y + 0.5f) * sy - 0.5f, 0.f), (float)(hi - 1));
    float px = fminf(fmaxf(((float)x + 0.5f) * sx - 0.5f, 0.f), (float)(wi - 1));
    float y0f = floorf(py), x0f = floorf(px);
    int y0 = (int)y0f, x0 = (int)x0f;
    int y1 = min(y0 + 1, hi - 1), x1 = min(x0 + 1, wi - 1);
    float wy = py - y0f, wx = px - x0f;

    const float* sp = in + (size_t)b * hi * wi;
    float r0 = sp[y0 * wi + x0] * (1.f - wx) + sp[y0 * wi + x1] * wx;
    float r1 = sp[y1 * wi + x0] * (1.f - wx) + sp[y1 * wi + x1] * wx;
    out[p] = r0 * (1.f - wy) + r1 * wy;
}

// ---------------------------------------------------------------------------
// softsplat scatter: acc[b, {(-f*ez).x, (-f*ez).y, ez}, h, w] += bilinear
// ---------------------------------------------------------------------------
__global__ void splat_k(const float* __restrict__ flow, const float* __restrict__ zz,
                        const float* __restrict__ tvec, int oneMinus,
                        float* __restrict__ acc, int h, int w, int n)
{
    int p = blockIdx.x * 256 + threadIdx.x;
    if (p >= n) return;
    const int hw = h * w;
    const int b = p / hw, pp = p % hw;
    const int y = pp / w, x = pp - y * w;

    float tt = tvec[b];
    if (oneMinus) tt = 1.f - tt;
    float f0 = tt * flow[((size_t)b * 2 + 0) * hw + pp];
    float f1 = tt * flow[((size_t)b * 2 + 1) * hw + pp];
    float ez = expf(zz[(size_t)b * hw + pp]);
    float v0 = -f0 * ez, v1 = -f1 * ez;

    float fx = (float)x + f0, fy = (float)y + f1;
    float x0f = floorf(fx), y0f = floorf(fy);
    int x0 = (int)x0f, y0 = (int)y0f;
    int x1 = x0 + 1, y1 = y0 + 1;
    float wx1 = fx - x0f, wy1 = fy - y0f;
    float wx0 = 1.f - wx1, wy0 = 1.f - wy1;

    float* a0 = acc + (size_t)b * 3 * hw;
    int cx[4] = {x0, x1, x0, x1};
    int cy[4] = {y0, y0, y1, y1};
    float cw[4] = {wx0 * wy0, wx1 * wy0, wx0 * wy1, wx1 * wy1};
#pragma unroll
    for (int k = 0; k < 4; k++) {
        if (cx[k] >= 0 && cx[k] < w && cy[k] >= 0 && cy[k] < h) {
            int q = cy[k] * w + cx[k];
            float wt = cw[k];
            atomicAdd(a0 + q, v0 * wt);
            atomicAdd(a0 + hw + q, v1 * wt);
            atomicAdd(a0 + 2 * hw + q, ez * wt);
        }
    }
}

__global__ void norm_k(const float* __restrict__ acc, float* __restrict__ flw,
                       int hw, int n)
{
    int p = blockIdx.x * 256 + threadIdx.x;
    if (p >= n) return;
    const int b = p / hw, pp = p % hw;
    float d = acc[((size_t)b * 3 + 2) * hw + pp] + 1e-7f;
    flw[((size_t)b * 2 + 0) * hw + pp] = acc[((size_t)b * 3 + 0) * hw + pp] / d;
    flw[((size_t)b * 2 + 1) * hw + pp] = acc[((size_t)b * 3 + 1) * hw + pp] / d;
}

// ---------------------------------------------------------------------------
// backwarp src (C channels) with flow, write into packed output tensor
// at channel offset c0 within CT total channels. grid.y = channel chunk (8).
// ---------------------------------------------------------------------------
__global__ void backwarp_out_k(const float* __restrict__ src, int C,
                               const float* __restrict__ flow, float* __restrict__ out,
                               int CT, int c0, int h, int w, int n)
{
    int p = blockIdx.x * 256 + threadIdx.x;
    if (p >= n) return;
    const int hw = h * w;
    const int b = p / hw, pp = p % hw;
    const int y = pp / w, x = pp - y * w;

    float f0 = flow[((size_t)b * 2 + 0) * hw + pp];
    float f1 = flow[((size_t)b * 2 + 1) * hw + pp];
    float px = fminf(fmaxf((float)x + f0, 0.f), (float)(w - 1));
    float py = fminf(fmaxf((float)y + f1, 0.f), (float)(h - 1));
    float x0f = floorf(px), y0f = floorf(py);
    int x0 = (int)x0f, y0 = (int)y0f;
    int x1 = min(x0 + 1, w - 1), y1 = min(y0 + 1, h - 1);
    float wx = px - x0f, wy = py - y0f;
    float w00 = (1.f - wx) * (1.f - wy), w10 = wx * (1.f - wy);
    float w01 = (1.f - wx) * wy,        w11 = wx * wy;

    int cbeg = blockIdx.y * 8;
    int cend = min(cbeg + 8, C);
#pragma unroll 4
    for (int c = cbeg; c < cend; c++) {
        const float* sp = src + ((size_t)b * C + c) * hw;
        float g = sp[y0 * w + x0] * w00 + sp[y0 * w + x1] * w10 +
                  sp[y1 * w + x0] * w01 + sp[y1 * w + x1] * w11;
        out[(((size_t)b * CT + c0 + c) * h + y) * w + x] = g;
    }
}

// ---------------------------------------------------------------------------
// Orchestration
// ---------------------------------------------------------------------------
static inline int cdiv(int a, int b) { return (a + b - 1) / b; }

// dynamic smem bytes for a conv instantiation
static inline int conv_smem(int STRIDE, int PY, int CHUNK)
{
    int tsw = 16 * STRIDE + 2;
    int tsh = 8 * PY * STRIDE + 2;
    return 2 * CHUNK * (tsw * tsh + 288) * 4;
}

extern "C" void kernel_launch(void* const* d_in, const int* in_sizes, int n_in,
                              void* d_out, int out_size)
{
    const float* in0   = (const float*)d_in[0];
    const float* in1   = (const float*)d_in[1];
    const float* tvec  = (const float*)d_in[2];
    const float* f01[3] = {(const float*)d_in[3], (const float*)d_in[4], (const float*)d_in[5]};
    const float* f10[3] = {(const float*)d_in[6], (const float*)d_in[7], (const float*)d_in[8]};
    const float* W[6]  = {(const float*)d_in[9],  (const float*)d_in[11], (const float*)d_in[13],
                          (const float*)d_in[15], (const float*)d_in[17], (const float*)d_in[19]};
    const float* Bs[6] = {(const float*)d_in[10], (const float*)d_in[12], (const float*)d_in[14],
                          (const float*)d_in[16], (const float*)d_in[18], (const float*)d_in[20]};
    const float* prelu  = (const float*)d_in[21];
    const float* pscale = (const float*)d_in[22];
    float* out = (float*)d_out;

    float* S = nullptr;
    cudaGetSymbolAddress((void**)&S, g_scratch);

    // dynamic smem opt-in (host API, not captured; idempotent)
    const int sm1   = conv_smem(1, 4, 3);   // conv1
    const int sm18  = conv_smem(1, 4, 8);   // stride1 CHUNK8
    const int sm28  = conv_smem(2, 2, 8);   // stride2 CHUNK8
    cudaFuncSetAttribute((const void*)conv3x3_k<3, 1, 4, 3>,  cudaFuncAttributeMaxDynamicSharedMemorySize, sm1);
    cudaFuncSetAttribute((const void*)conv3x3_k<32, 1, 4, 8>, cudaFuncAttributeMaxDynamicSharedMemorySize, sm18);
    cudaFuncSetAttribute((const void*)conv3x3_k<32, 2, 2, 8>, cudaFuncAttributeMaxDynamicSharedMemorySize, sm28);
    cudaFuncSetAttribute((const void*)conv3x3_k<64, 1, 4, 8>, cudaFuncAttributeMaxDynamicSharedMemorySize, sm18);
    cudaFuncSetAttribute((const void*)conv3x3_k<64, 2, 2, 8>, cudaFuncAttributeMaxDynamicSharedMemorySize, sm28);
    cudaFuncSetAttribute((const void*)conv3x3_k<96, 1, 4, 8>, cudaFuncAttributeMaxDynamicSharedMemorySize, sm18);

    // ---- feature extraction for both images ----
    for (int img = 0; img < 2; img++) {
        const float* x = img ? in1 : in0;
        float* fea1 = S + (img ? O_FEA1_1 : O_FEA1_0);
        float* fea2 = S + (img ? O_FEA2_1 : O_FEA2_0);
        float* fea3 = S + (img ? O_FEA3_1 : O_FEA3_0);

        conv3x3_k<3, 1, 4, 3><<<dim3(32, 16, 2), 256, sm1>>>(x,         W[0], Bs[0], prelu, 0, S + O_T1, 512, 512, 32, 1);
        conv3x3_k<32, 1, 4, 8><<<dim3(32, 16, 2), 256, sm18>>>(S + O_T1, W[1], Bs[1], prelu, 1, fea1,     512, 512, 32, 1);
        conv3x3_k<32, 2, 2, 8><<<dim3(16, 16, 4), 256, sm28>>>(fea1,     W[2], Bs[2], prelu, 2, S + O_T2, 512, 512, 64, 2);
        conv3x3_k<64, 1, 4, 8><<<dim3(16, 8, 4), 256, sm18>>>(S + O_T2,  W[3], Bs[3], prelu, 3, fea2,     256, 256, 64, 2);
        conv3x3_k<64, 2, 2, 8><<<dim3(8, 8, 6), 256, sm28>>>(fea2,       W[4], Bs[4], prelu, 4, S + O_T3, 256, 256, 96, 3);
        conv3x3_k<96, 1, 4, 8><<<dim3(8, 4, 6), 256, sm18>>>(S + O_T3,   W[5], Bs[5], prelu, 5, fea3,     128, 128, 96, 3);
    }

    float* L0 = out;                 // (B,70,512,512)
    float* L1 = out + 36700160ull;   // (B,128,256,256)
    float* L2 = out + 53477376ull;   // (B,192,128,128)

    // ---- splat maps, both directions ----
    for (int dir = 0; dir < 2; dir++) {
        const float* i0 = dir ? in1 : in0;
        const float* i1sec = dir ? in0 : in1;
        const float* const* fl = dir ? f10 : f01;
        const float* fea1 = S + (dir ? O_FEA1_1 : O_FEA1_0);
        const float* fea2 = S + (dir ? O_FEA2_1 : O_FEA2_0);
        const float* fea3 = S + (dir ? O_FEA3_1 : O_FEA3_0);

        const int n0 = BB * 512 * 512;
        z_kernel<<<cdiv(n0, 256), 256>>>(i0, i1sec, fl[0], pscale, S + O_Z, 512, 512, n0);
        const int nr1 = BB * 256 * 256, nr2 = BB * 128 * 128;
        resize_k<<<cdiv(nr1, 256), 256>>>(S + O_Z, S + O_ZR1, 512, 512, 256, 256, nr1);
        resize_k<<<cdiv(nr2, 256), 256>>>(S + O_Z, S + O_ZR2, 512, 512, 128, 128, nr2);

        for (int s = 0; s < 3; s++) {
            const int hh = 512 >> s, ww = 512 >> s;
            const int hw = hh * ww, n = BB * hw;
            const float* zl = (s == 0) ? (S + O_Z) : ((s == 1) ? (S + O_ZR1) : (S + O_ZR2));

            cudaMemsetAsync(S + O_ACC, 0, sizeof(float) * (size_t)BB * 3 * hw, 0);
            splat_k<<<cdiv(n, 256), 256>>>(fl[s], zl, tvec, dir, S + O_ACC, hh, ww, n);
            norm_k<<<cdiv(n, 256), 256>>>(S + O_ACC, S + O_FLOW, hw, n);

            if (s == 0) {
                backwarp_out_k<<<dim3(cdiv(n, 256), 1), 256>>>(i0,   3,  S + O_FLOW, L0, 70, dir ? 35 : 0, hh, ww, n);
                backwarp_out_k<<<dim3(cdiv(n, 256), 4), 256>>>(fea1, 32, S + O_FLOW, L0, 70, dir ? 38 : 3, hh, ww, n);
            } else if (s == 1) {
                backwarp_out_k<<<dim3(cdiv(n, 256), 8), 256>>>(fea2, 64, S + O_FLOW, L1, 128, dir ? 64 : 0, hh, ww, n);
            } else {
                backwarp_out_k<<<dim3(cdiv(n, 256), 12), 256>>>(fea3, 96, S + O_FLOW, L2, 192, dir ? 96 : 0, hh, ww, n);
            }
        }
    }
}

// round 9
// speedup vs baseline: 1.8592x; 1.0385x over previous
#include <cuda_runtime.h>
#include <cstdint>

#define BB 2
#define EPS 1e-7f

// ---------------------------------------------------------------------------
// scratch layout (floats) — per-image conv buffers now disjoint (batched convs)
// ---------------------------------------------------------------------------
#define SZ_T1P   16777216ull   // BB*32*512*512
#define SZ_F1P   16777216ull
#define SZ_T2P    8388608ull   // BB*64*256*256
#define SZ_F2P    8388608ull
#define SZ_T3P    3145728ull   // BB*96*128*128
#define SZ_F3P    3145728ull

#define O_T1_0   0ull
#define O_T1_1   (O_T1_0 + SZ_T1P)
#define O_F1_0   (O_T1_1 + SZ_T1P)
#define O_F1_1   (O_F1_0 + SZ_F1P)
#define O_T2_0   (O_F1_1 + SZ_F1P)
#define O_T2_1   (O_T2_0 + SZ_T2P)
#define O_F2_0   (O_T2_1 + SZ_T2P)
#define O_F2_1   (O_F2_0 + SZ_F2P)
#define O_T3_0   (O_F2_1 + SZ_F2P)
#define O_T3_1   (O_T3_0 + SZ_T3P)
#define O_F3_0   (O_T3_1 + SZ_T3P)
#define O_F3_1   (O_F3_0 + SZ_F3P)
#define O_Z      (O_F3_1 + SZ_F3P)
#define O_ZR1    (O_Z + 524288ull)
#define O_ZR2    (O_ZR1 + 131072ull)
#define O_ACC    (O_ZR2 + 32768ull)
// per-dir acc: s0 1572864, s1 393216, s2 98304 -> 2064384; two dirs
#define ACC_PER_DIR 2064384ull
#define ACC_TOTAL   (2ull * ACC_PER_DIR)
#define SCRATCH_TOTAL (O_ACC + ACC_TOTAL)

__device__ float g_scratch[SCRATCH_TOTAL];

// ---------------------------------------------------------------------------
// cp.async helpers
// ---------------------------------------------------------------------------
__device__ __forceinline__ void cp_async4(uint32_t smem_dst, const void* gsrc, bool pred)
{
    int sz = pred ? 4 : 0;
    asm volatile("cp.async.ca.shared.global [%0], [%1], 4, %2;\n"
                 :: "r"(smem_dst), "l"(gsrc), "r"(sz));
}
__device__ __forceinline__ void cp_commit() { asm volatile("cp.async.commit_group;\n"); }
template <int N>
__device__ __forceinline__ void cp_wait() { asm volatile("cp.async.wait_group %0;\n" :: "n"(N)); }

// ---------------------------------------------------------------------------
// Register-tiled 3x3 conv + PReLU, IC-chunked, double-buffered cp.async.
// BOTH images batched in grid.z: z = (img*BB + b)*ocBlocks + ocb.
// ---------------------------------------------------------------------------
template <int IC, int STRIDE, int PY, int CHUNK>
__global__ __launch_bounds__(256, 2)
void conv3x3_k(const float* __restrict__ in0, const float* __restrict__ in1,
               const float* __restrict__ wgt,
               const float* __restrict__ bias, const float* __restrict__ prelu_a,
               int aidx, float* __restrict__ out0, float* __restrict__ out1,
               int Hin, int Win, int OC, int ocBlocks)
{
    static_assert(IC % CHUNK == 0, "IC % CHUNK");
    constexpr int PX = 2;
    constexpr int OUT_TW = 16;
    constexpr int OUT_TH = 8 * PY;
    constexpr int TS_W = OUT_TW * STRIDE + 2;
    constexpr int TS_H = OUT_TH * STRIDE + 2;
    constexpr int TSZ  = TS_W * TS_H;
    constexpr int PW = (PX - 1) * STRIDE + 3;
    constexpr int PH = (PY - 1) * STRIDE + 3;
    constexpr int NCH = IC / CHUNK;
    constexpr int BUF = CHUNK * TSZ + CHUNK * 288;

    extern __shared__ __align__(16) float s_mem[];

    const int tid = threadIdx.x;
    const int oo  = tid & 3;
    const int slot = tid >> 2;
    const int sx = slot & 7;
    const int sy = slot >> 3;

    const int zper = BB * ocBlocks;
    const int img  = blockIdx.z / zper;
    const int rem  = blockIdx.z - img * zper;
    const int b    = rem / ocBlocks;
    const int ocb  = rem - b * ocBlocks;
    const float* __restrict__ in  = img ? in1 : in0;
    float* __restrict__ out = img ? out1 : out0;

    const int oc0 = ocb * 32;
    const int Hout = Hin / STRIDE;
    const int Wout = Win / STRIDE;

    const int ox = blockIdx.x * OUT_TW + sx * PX;
    const int oy = blockIdx.y * OUT_TH + sy * PY;
    const int ix0 = blockIdx.x * OUT_TW * STRIDE - 1;
    const int iy0 = blockIdx.y * OUT_TH * STRIDE - 1;

    const int ly = sy * PY * STRIDE;
    const int lx = sx * PX * STRIDE;

    auto stage = [&](int ci, int bufIdx) {
        float* sb = s_mem + bufIdx * BUF;
        const uint32_t s_in_a = (uint32_t)__cvta_generic_to_shared(sb);
        const uint32_t s_w_a  = (uint32_t)__cvta_generic_to_shared(sb + CHUNK * TSZ);
        const int cb = ci * CHUNK;
#pragma unroll 4
        for (int i = tid; i < CHUNK * TSZ; i += 256) {
            int c = i / TSZ;
            int j = i - c * TSZ;
            int gy = iy0 + j / TS_W;
            int gx = ix0 + j % TS_W;
            bool ok = (gy >= 0 && gy < Hin && gx >= 0 && gx < Win);
            const float* src = in + ((size_t)(b * IC + cb + c)) * Hin * Win
                                  + (ok ? (gy * Win + gx) : 0);
            cp_async4(s_in_a + 4u * i, src, ok);
        }
#pragma unroll 4
        for (int i = tid; i < CHUNK * 288; i += 256) {
            int c = i / 288;
            int r = i - c * 288;
            int k = r >> 5, oc = r & 31;
            cp_async4(s_w_a + 4u * i,
                      &wgt[((size_t)(oc0 + oc) * IC + cb + c) * 9 + k], true);
        }
        cp_commit();
    };

    float acc[8][PX * PY];
#pragma unroll
    for (int o = 0; o < 8; o++)
#pragma unroll
        for (int p = 0; p < PX * PY; p++) acc[o][p] = 0.f;

    stage(0, 0);

    for (int ci = 0; ci < NCH; ci++) {
        const int cur = ci & 1;
        if (ci + 1 < NCH) stage(ci + 1, cur ^ 1);

        if (ci + 1 < NCH) cp_wait<1>(); else cp_wait<0>();
        __syncthreads();

        const float* s_in = s_mem + cur * BUF;
        const float* s_w  = s_in + CHUNK * TSZ;

#pragma unroll
        for (int c = 0; c < CHUNK; c++) {
            float v[PH][PW];
#pragma unroll
            for (int r = 0; r < PH; r++)
#pragma unroll
                for (int cc = 0; cc < PW; cc++)
                    v[r][cc] = s_in[c * TSZ + (ly + r) * TS_W + lx + cc];

#pragma unroll
            for (int k = 0; k < 9; k++) {
                const int ky = k / 3, kx = k % 3;
                const float4 wA = *reinterpret_cast<const float4*>(&s_w[c * 288 + k * 32 + oo * 8]);
                const float4 wB = *reinterpret_cast<const float4*>(&s_w[c * 288 + k * 32 + oo * 8 + 4]);
                const float w8[8] = {wA.x, wA.y, wA.z, wA.w, wB.x, wB.y, wB.z, wB.w};
#pragma unroll
                for (int o = 0; o < 8; o++)
#pragma unroll
                    for (int py = 0; py < PY; py++)
#pragma unroll
                        for (int px = 0; px < PX; px++)
                            acc[o][py * PX + px] =
                                fmaf(v[py * STRIDE + ky][px * STRIDE + kx], w8[o],
                                     acc[o][py * PX + px]);
            }
        }
        __syncthreads();
    }

    const float slope = prelu_a[aidx];
#pragma unroll
    for (int o = 0; o < 8; o++) {
        const int oc = oc0 + oo * 8 + o;
        const float bv = bias[oc];
        float* op = out + (((size_t)b * OC + oc) * Hout) * Wout;
#pragma unroll
        for (int py = 0; py < PY; py++) {
            float v0 = acc[o][py * PX + 0] + bv;
            float v1 = acc[o][py * PX + 1] + bv;
            if (v0 < 0.f) v0 *= slope;
            if (v1 < 0.f) v1 *= slope;
            *reinterpret_cast<float2*>(&op[(size_t)(oy + py) * Wout + ox]) =
                make_float2(v0, v1);
        }
    }
}

// ---------------------------------------------------------------------------
// z = param_scale * mean_c |p0 - backwarp(p1, flow)|
// ---------------------------------------------------------------------------
__global__ void z_kernel(const float* __restrict__ i0, const float* __restrict__ i1,
                         const float* __restrict__ flow, const float* __restrict__ pscale,
                         float* __restrict__ z, int h, int w, int n)
{
    int p = blockIdx.x * 256 + threadIdx.x;
    if (p >= n) return;
    const int hw = h * w;
    const int b = p / hw, pp = p % hw;
    const int y = pp / w, x = pp - y * w;

    float f0 = flow[((size_t)b * 2 + 0) * hw + pp];
    float f1 = flow[((size_t)b * 2 + 1) * hw + pp];
    float px = fminf(fmaxf((float)x + f0, 0.f), (float)(w - 1));
    float py = fminf(fmaxf((float)y + f1, 0.f), (float)(h - 1));
    float x0f = floorf(px), y0f = floorf(py);
    int x0 = (int)x0f, y0 = (int)y0f;
    int x1 = min(x0 + 1, w - 1), y1 = min(y0 + 1, h - 1);
    float wx = px - x0f, wy = py - y0f;
    float w00 = (1.f - wx) * (1.f - wy), w10 = wx * (1.f - wy);
    float w01 = (1.f - wx) * wy,        w11 = wx * wy;

    float err = 0.f;
#pragma unroll
    for (int c = 0; c < 3; c++) {
        const float* sp = i1 + ((size_t)(b * 3 + c)) * hw;
        float g = sp[y0 * w + x0] * w00 + sp[y0 * w + x1] * w10 +
                  sp[y1 * w + x0] * w01 + sp[y1 * w + x1] * w11;
        float pg = 2.f * g - 1.f;
        float p0 = 2.f * i0[((size_t)(b * 3 + c)) * hw + pp] - 1.f;
        err += fabsf(p0 - pg);
    }
    err *= (1.f / 3.f);
    z[p] = pscale[0] * err;
}

// ---------------------------------------------------------------------------
// bilinear resize, single channel
// ---------------------------------------------------------------------------
__global__ void resize_k(const float* __restrict__ in, float* __restrict__ out,
                         int hi, int wi, int ho, int wo, int n)
{
    int p = blockIdx.x * 256 + threadIdx.x;
    if (p >= n) return;
    const int hwO = ho * wo;
    const int b = p / hwO, pp = p % hwO;
    const int y = pp / wo, x = pp - y * wo;

    float sy = (float)hi / (float)ho;
    float sx = (float)wi / (float)wo;
    float py = fminf(fmaxf(((float)y + 0.5f) * sy - 0.5f, 0.f), (float)(hi - 1));
    float px = fminf(fmaxf(((float)x + 0.5f) * sx - 0.5f, 0.f), (float)(wi - 1));
    float y0f = floorf(py), x0f = floorf(px);
    int y0 = (int)y0f, x0 = (int)x0f;
    int y1 = min(y0 + 1, hi - 1), x1 = min(x0 + 1, wi - 1);
    float wy = py - y0f, wx = px - x0f;

    const float* sp = in + (size_t)b * hi * wi;
    float r0 = sp[y0 * wi + x0] * (1.f - wx) + sp[y0 * wi + x1] * wx;
    float r1 = sp[y1 * wi + x0] * (1.f - wx) + sp[y1 * wi + x1] * wx;
    out[p] = r0 * (1.f - wy) + r1 * wy;
}

// ---------------------------------------------------------------------------
// softsplat scatter into per-(dir,s) acc
// ---------------------------------------------------------------------------
__global__ void splat_k(const float* __restrict__ flow, const float* __restrict__ zz,
                        const float* __restrict__ tvec, int oneMinus,
                        float* __restrict__ acc, int h, int w, int n)
{
    int p = blockIdx.x * 256 + threadIdx.x;
    if (p >= n) return;
    const int hw = h * w;
    const int b = p / hw, pp = p % hw;
    const int y = pp / w, x = pp - y * w;

    float tt = tvec[b];
    if (oneMinus) tt = 1.f - tt;
    float f0 = tt * flow[((size_t)b * 2 + 0) * hw + pp];
    float f1 = tt * flow[((size_t)b * 2 + 1) * hw + pp];
    float ez = expf(zz[(size_t)b * hw + pp]);
    float v0 = -f0 * ez, v1 = -f1 * ez;

    float fx = (float)x + f0, fy = (float)y + f1;
    float x0f = floorf(fx), y0f = floorf(fy);
    int x0 = (int)x0f, y0 = (int)y0f;
    int x1 = x0 + 1, y1 = y0 + 1;
    float wx1 = fx - x0f, wy1 = fy - y0f;
    float wx0 = 1.f - wx1, wy0 = 1.f - wy1;

    float* a0 = acc + (size_t)b * 3 * hw;
    int cx[4] = {x0, x1, x0, x1};
    int cy[4] = {y0, y0, y1, y1};
    float cw[4] = {wx0 * wy0, wx1 * wy0, wx0 * wy1, wx1 * wy1};
#pragma unroll
    for (int k = 0; k < 4; k++) {
        if (cx[k] >= 0 && cx[k] < w && cy[k] >= 0 && cy[k] < h) {
            int q = cy[k] * w + cx[k];
            float wt = cw[k];
            atomicAdd(a0 + q, v0 * wt);
            atomicAdd(a0 + hw + q, v1 * wt);
            atomicAdd(a0 + 2 * hw + q, ez * wt);
        }
    }
}

// ---------------------------------------------------------------------------
// backwarp with flow normalization FUSED (reads acc, divides inline).
// grid.y = channel chunk (8 channels each).
// ---------------------------------------------------------------------------
__global__ void backwarp_out_k(const float* __restrict__ src, int C,
                               const float* __restrict__ acc, float* __restrict__ out,
                               int CT, int c0, int h, int w, int n)
{
    int p = blockIdx.x * 256 + threadIdx.x;
    if (p >= n) return;
    const int hw = h * w;
    const int b = p / hw, pp = p % hw;
    const int y = pp / w, x = pp - y * w;

    const float* ab = acc + (size_t)b * 3 * hw;
    float d  = ab[2 * hw + pp] + EPS;
    float f0 = ab[pp] / d;
    float f1 = ab[hw + pp] / d;

    float px = fminf(fmaxf((float)x + f0, 0.f), (float)(w - 1));
    float py = fminf(fmaxf((float)y + f1, 0.f), (float)(h - 1));
    float x0f = floorf(px), y0f = floorf(py);
    int x0 = (int)x0f, y0 = (int)y0f;
    int x1 = min(x0 + 1, w - 1), y1 = min(y0 + 1, h - 1);
    float wx = px - x0f, wy = py - y0f;
    float w00 = (1.f - wx) * (1.f - wy), w10 = wx * (1.f - wy);
    float w01 = (1.f - wx) * wy,        w11 = wx * wy;

    int cbeg = blockIdx.y * 8;
    int cend = min(cbeg + 8, C);
#pragma unroll 4
    for (int c = cbeg; c < cend; c++) {
        const float* sp = src + ((size_t)b * C + c) * hw;
        float g = sp[y0 * w + x0] * w00 + sp[y0 * w + x1] * w10 +
                  sp[y1 * w + x0] * w01 + sp[y1 * w + x1] * w11;
        out[(((size_t)b * CT + c0 + c) * h + y) * w + x] = g;
    }
}

// ---------------------------------------------------------------------------
// Orchestration
// ---------------------------------------------------------------------------
static inline int cdiv(int a, int b) { return (a + b - 1) / b; }

static inline int conv_smem(int STRIDE, int PY, int CHUNK)
{
    int tsw = 16 * STRIDE + 2;
    int tsh = 8 * PY * STRIDE + 2;
    return 2 * CHUNK * (tsw * tsh + 288) * 4;
}

extern "C" void kernel_launch(void* const* d_in, const int* in_sizes, int n_in,
                              void* d_out, int out_size)
{
    const float* in0   = (const float*)d_in[0];
    const float* in1   = (const float*)d_in[1];
    const float* tvec  = (const float*)d_in[2];
    const float* f01[3] = {(const float*)d_in[3], (const float*)d_in[4], (const float*)d_in[5]};
    const float* f10[3] = {(const float*)d_in[6], (const float*)d_in[7], (const float*)d_in[8]};
    const float* W[6]  = {(const float*)d_in[9],  (const float*)d_in[11], (const float*)d_in[13],
                          (const float*)d_in[15], (const float*)d_in[17], (const float*)d_in[19]};
    const float* Bs[6] = {(const float*)d_in[10], (const float*)d_in[12], (const float*)d_in[14],
                          (const float*)d_in[16], (const float*)d_in[18], (const float*)d_in[20]};
    const float* prelu  = (const float*)d_in[21];
    const float* pscale = (const float*)d_in[22];
    float* out = (float*)d_out;

    float* S = nullptr;
    cudaGetSymbolAddress((void**)&S, g_scratch);

    const int sm1   = conv_smem(1, 4, 3);
    const int sm18  = conv_smem(1, 4, 8);
    const int sm28  = conv_smem(2, 2, 8);
    cudaFuncSetAttribute((const void*)conv3x3_k<3, 1, 4, 3>,  cudaFuncAttributeMaxDynamicSharedMemorySize, sm1);
    cudaFuncSetAttribute((const void*)conv3x3_k<32, 1, 4, 8>, cudaFuncAttributeMaxDynamicSharedMemorySize, sm18);
    cudaFuncSetAttribute((const void*)conv3x3_k<32, 2, 2, 8>, cudaFuncAttributeMaxDynamicSharedMemorySize, sm28);
    cudaFuncSetAttribute((const void*)conv3x3_k<64, 1, 4, 8>, cudaFuncAttributeMaxDynamicSharedMemorySize, sm18);
    cudaFuncSetAttribute((const void*)conv3x3_k<64, 2, 2, 8>, cudaFuncAttributeMaxDynamicSharedMemorySize, sm28);
    cudaFuncSetAttribute((const void*)conv3x3_k<96, 1, 4, 8>, cudaFuncAttributeMaxDynamicSharedMemorySize, sm18);

    // single memset of all (dir,s) acc regions
    cudaMemsetAsync(S + O_ACC, 0, sizeof(float) * ACC_TOTAL, 0);

    // ---- feature extraction, both images batched per launch ----
    conv3x3_k<3, 1, 4, 3><<<dim3(32, 16, 4), 256, sm1>>>(in0, in1, W[0], Bs[0], prelu, 0,
                                                          S + O_T1_0, S + O_T1_1, 512, 512, 32, 1);
    conv3x3_k<32, 1, 4, 8><<<dim3(32, 16, 4), 256, sm18>>>(S + O_T1_0, S + O_T1_1, W[1], Bs[1], prelu, 1,
                                                            S + O_F1_0, S + O_F1_1, 512, 512, 32, 1);
    conv3x3_k<32, 2, 2, 8><<<dim3(16, 16, 8), 256, sm28>>>(S + O_F1_0, S + O_F1_1, W[2], Bs[2], prelu, 2,
                                                            S + O_T2_0, S + O_T2_1, 512, 512, 64, 2);
    conv3x3_k<64, 1, 4, 8><<<dim3(16, 8, 8), 256, sm18>>>(S + O_T2_0, S + O_T2_1, W[3], Bs[3], prelu, 3,
                                                           S + O_F2_0, S + O_F2_1, 256, 256, 64, 2);
    conv3x3_k<64, 2, 2, 8><<<dim3(8, 8, 12), 256, sm28>>>(S + O_F2_0, S + O_F2_1, W[4], Bs[4], prelu, 4,
                                                           S + O_T3_0, S + O_T3_1, 256, 256, 96, 3);
    conv3x3_k<96, 1, 4, 8><<<dim3(8, 4, 12), 256, sm18>>>(S + O_T3_0, S + O_T3_1, W[5], Bs[5], prelu, 5,
                                                           S + O_F3_0, S + O_F3_1, 128, 128, 96, 3);

    float* L0 = out;                 // (B,70,512,512)
    float* L1 = out + 36700160ull;   // (B,128,256,256)
    float* L2 = out + 53477376ull;   // (B,192,128,128)

    for (int dir = 0; dir < 2; dir++) {
        const float* i0 = dir ? in1 : in0;
        const float* i1sec = dir ? in0 : in1;
        const float* const* fl = dir ? f10 : f01;
        const float* fea1 = S + (dir ? O_F1_1 : O_F1_0);
        const float* fea2 = S + (dir ? O_F2_1 : O_F2_0);
        const float* fea3 = S + (dir ? O_F3_1 : O_F3_0);

        float* acc0 = S + O_ACC + (size_t)dir * ACC_PER_DIR;
        float* acc1 = acc0 + 1572864;
        float* acc2 = acc0 + 1966080;
        float* accS[3] = {acc0, acc1, acc2};

        const int n0 = BB * 512 * 512;
        z_kernel<<<cdiv(n0, 256), 256>>>(i0, i1sec, fl[0], pscale, S + O_Z, 512, 512, n0);
        const int nr1 = BB * 256 * 256, nr2 = BB * 128 * 128;
        resize_k<<<cdiv(nr1, 256), 256>>>(S + O_Z, S + O_ZR1, 512, 512, 256, 256, nr1);
        resize_k<<<cdiv(nr2, 256), 256>>>(S + O_Z, S + O_ZR2, 512, 512, 128, 128, nr2);

        for (int s = 0; s < 3; s++) {
            const int hh = 512 >> s, ww = 512 >> s;
            const int hw = hh * ww, n = BB * hw;
            const float* zl = (s == 0) ? (S + O_Z) : ((s == 1) ? (S + O_ZR1) : (S + O_ZR2));

            splat_k<<<cdiv(n, 256), 256>>>(fl[s], zl, tvec, dir, accS[s], hh, ww, n);

            if (s == 0) {
                backwarp_out_k<<<dim3(cdiv(n, 256), 1), 256>>>(i0,   3,  accS[s], L0, 70, dir ? 35 : 0, hh, ww, n);
                backwarp_out_k<<<dim3(cdiv(n, 256), 4), 256>>>(fea1, 32, accS[s], L0, 70, dir ? 38 : 3, hh, ww, n);
            } else if (s == 1) {
                backwarp_out_k<<<dim3(cdiv(n, 256), 8), 256>>>(fea2, 64, accS[s], L1, 128, dir ? 64 : 0, hh, ww, n);
            } else {
                backwarp_out_k<<<dim3(cdiv(n, 256), 12), 256>>>(fea3, 96, accS[s], L2, 192, dir ? 96 : 0, hh, ww, n);
            }
        }
    }
}